// round 2
// baseline (speedup 1.0000x reference)
#include <cuda_runtime.h>

#define Bn 4
#define Vn 4096
#define Kn 128
#define Cn 128
#define NS 16
#define SA 20

// ---- scratch (allocation-free rule: __device__ globals) ----
__device__ float g_GXE[Bn*Vn*Kn], g_GYE[Bn*Vn*Kn];
__device__ float g_x[Bn*Vn*Cn], g_xd[Bn*Vn*Cn], g_gx[Bn*Vn*Cn], g_gy[Bn*Vn*Cn];
__device__ float g_br[Bn*Vn*Cn], g_bi[Bn*Vn*Cn], g_gf[Bn*Vn*Cn];
__device__ float g_h0[Bn*Vn*Cn], g_h1[Bn*Vn*Cn];
__device__ float g_Sp[Bn*NS*Kn*Cn], g_D[Bn*Kn*Cn];

__device__ __forceinline__ float tf32_hi(float x){
  unsigned u; asm("cvt.rna.tf32.f32 %0, %1;" : "=r"(u) : "f"(x));
  return __uint_as_float(u);
}
__device__ __forceinline__ void mma8(float* d, const unsigned* a, unsigned b0, unsigned b1){
  asm volatile("mma.sync.aligned.m16n8k8.row.col.f32.tf32.tf32.f32 "
               "{%0,%1,%2,%3},{%4,%5,%6,%7},{%8,%9},{%0,%1,%2,%3};"
               : "+f"(d[0]),"+f"(d[1]),"+f"(d[2]),"+f"(d[3])
               : "r"(a[0]),"r"(a[1]),"r"(a[2]),"r"(a[3]),"r"(b0),"r"(b1));
}

// stage A row-major [128m x 16k] (row stride lda) -> Ah/Al[m*SA+k]
__device__ __forceinline__ void stA(const float* A, int lda, float* H, float* L, int tid){
#pragma unroll
  for(int i=0;i<2;i++){
    int e=tid+i*256, m=e>>2, kq=(e&3)<<2;
    float4 v=*(const float4*)(A+(size_t)m*lda+kq);
    float hx=tf32_hi(v.x),hy=tf32_hi(v.y),hz=tf32_hi(v.z),hw=tf32_hi(v.w);
    *(float4*)(H+m*SA+kq)=make_float4(hx,hy,hz,hw);
    *(float4*)(L+m*SA+kq)=make_float4(tf32_hi(v.x-hx),tf32_hi(v.y-hy),tf32_hi(v.z-hz),tf32_hi(v.w-hw));
  }
}
// stage source row-major [16k x 128n] (row stride 128) TRANSPOSED -> H/L[n*SA+k]
// optional per-row scale rs[k] and uniform scale sc
__device__ __forceinline__ void stT(const float* Bg, const float* rs, float sc,
                                    float* H, float* L, int tid){
#pragma unroll
  for(int i=0;i<2;i++){
    int e=tid+i*256, k=e&15, nq=(e>>4)<<2;
    float s = rs ? sc*rs[k] : sc;
    float4 v=*(const float4*)(Bg+(size_t)k*128+nq);
    float ax=v.x*s, ay=v.y*s, az=v.z*s, aw=v.w*s;
    float hx=tf32_hi(ax),hy=tf32_hi(ay),hz=tf32_hi(az),hw=tf32_hi(aw);
    H[(nq+0)*SA+k]=hx; L[(nq+0)*SA+k]=tf32_hi(ax-hx);
    H[(nq+1)*SA+k]=hy; L[(nq+1)*SA+k]=tf32_hi(ay-hy);
    H[(nq+2)*SA+k]=hz; L[(nq+2)*SA+k]=tf32_hi(az-hz);
    H[(nq+3)*SA+k]=hw; L[(nq+3)*SA+k]=tf32_hi(aw-hw);
  }
}

// one 16-deep K step, 3xTF32, warp tile 32x64 (8 warps -> 128x128)
__device__ __forceinline__ void gstep(const float* Ah,const float* Al,
                                      const float* Bh,const float* Bl,
                                      float (&acc)[2][8][4], int wm,int wn,int lane){
  int r=lane>>2, c=lane&3;
#pragma unroll
  for(int ks=0;ks<16;ks+=8){
    unsigned ah[2][4], al[2][4];
#pragma unroll
    for(int mt=0;mt<2;mt++){
      const float* p=Ah+(wm*32+mt*16+r)*SA+ks+c;
      ah[mt][0]=__float_as_uint(p[0]); ah[mt][1]=__float_as_uint(p[8*SA]);
      ah[mt][2]=__float_as_uint(p[4]); ah[mt][3]=__float_as_uint(p[8*SA+4]);
      const float* q=Al+(wm*32+mt*16+r)*SA+ks+c;
      al[mt][0]=__float_as_uint(q[0]); al[mt][1]=__float_as_uint(q[8*SA]);
      al[mt][2]=__float_as_uint(q[4]); al[mt][3]=__float_as_uint(q[8*SA+4]);
    }
#pragma unroll
    for(int nt=0;nt<8;nt++){
      const float* p=Bh+(wn*64+nt*8+r)*SA+ks+c;
      unsigned bh0=__float_as_uint(p[0]), bh1=__float_as_uint(p[4]);
      const float* q=Bl+(wn*64+nt*8+r)*SA+ks+c;
      unsigned bl0=__float_as_uint(q[0]), bl1=__float_as_uint(q[4]);
#pragma unroll
      for(int mt=0;mt<2;mt++){
        mma8(acc[mt][nt],ah[mt],bh0,bh1);
        mma8(acc[mt][nt],ah[mt],bl0,bl1);
        mma8(acc[mt][nt],al[mt],bh0,bh1);
      }
    }
  }
}

struct GArgs {
  const float* A[3][3];   // [z][seg]
  float* C[3];            // [z]
  const float* Bs[3]; long sB[3]; float bsc[3]; int kst[3];
  int lda, nseg;
  long sA, sC;
  const float* bias; const float* res; long sRes;
  int act;                // 1 = relu
};

__global__ void __launch_bounds__(256) k_gemm(GArgs ga){
  __shared__ float Ah[128*SA],Al[128*SA],Bh[128*SA],Bl[128*SA];
  int tid=threadIdx.x, lane=tid&31, w=tid>>5, wm=w&3, wn=w>>2;
  float acc[2][8][4]={};
  int mt=blockIdx.x, b=blockIdx.y, z=blockIdx.z;
  for(int s=0;s<ga.nseg;s++){
    const float* As = ga.A[z][s] + (size_t)b*ga.sA + (size_t)mt*128*ga.lda;
    const float* Bsrc = ga.Bs[s] + (size_t)b*ga.sB[s];
    for(int k0=0;k0<ga.kst[s];k0++){
      stA(As + k0*16, ga.lda, Ah, Al, tid);
      stT(Bsrc + (size_t)k0*16*128, nullptr, ga.bsc[s], Bh, Bl, tid);
      __syncthreads();
      gstep(Ah,Al,Bh,Bl,acc,wm,wn,lane);
      __syncthreads();
    }
  }
  float* Cg = ga.C[z] + (size_t)b*ga.sC + (size_t)mt*128*Cn;
  const float* Rg = ga.res ? ga.res + (size_t)b*ga.sRes + (size_t)mt*128*Cn : nullptr;
  int er=lane>>2, ec=lane&3;
#pragma unroll
  for(int m2=0;m2<2;m2++)
#pragma unroll
  for(int nt=0;nt<8;nt++){
    int row=wm*32+m2*16+er, col=wn*64+nt*8+2*ec;
    float* av=acc[m2][nt];
#pragma unroll
    for(int rr=0;rr<2;rr++){
      int R=row+rr*8;
      float v0=av[rr*2], v1=av[rr*2+1];
      if(ga.bias){ v0+=ga.bias[col]; v1+=ga.bias[col+1]; }
      if(ga.act==1){ v0=fmaxf(v0,0.f); v1=fmaxf(v1,0.f); }
      if(Rg){ v0+=Rg[(size_t)R*Cn+col]; v1+=Rg[(size_t)R*Cn+col+1]; }
      Cg[(size_t)R*Cn+col]=v0; Cg[(size_t)R*Cn+col+1]=v1;
    }
  }
}

// x_spec split-K partials: Sp[b,sp] = E[v0:v0+256]^T @ (x*mass)[v0:v0+256]
__global__ void __launch_bounds__(256) k_spec(const float* E, const float* mass){
  __shared__ float Ah[128*SA],Al[128*SA],Bh[128*SA],Bl[128*SA];
  int tid=threadIdx.x, lane=tid&31, w=tid>>5, wm=w&3, wn=w>>2;
  float acc[2][8][4]={};
  int b=blockIdx.x, sp=blockIdx.y;
  const float* Eb=E+(size_t)b*Vn*Kn;
  const float* Xb=g_x+(size_t)b*Vn*Cn;
  const float* Mb=mass+(size_t)b*Vn;
  int v0=sp*(Vn/NS);
  for(int k0=0;k0<Vn/NS;k0+=16){
    int v=v0+k0;
    stT(Eb+(size_t)v*Kn, nullptr, 1.f, Ah, Al, tid);  // Ah[k_eig][vv]
    stT(Xb+(size_t)v*Cn, Mb+v, 1.f, Bh, Bl, tid);     // Bt[c][vv] * mass
    __syncthreads();
    gstep(Ah,Al,Bh,Bl,acc,wm,wn,lane);
    __syncthreads();
  }
  float* Cg=g_Sp+(size_t)(b*NS+sp)*Kn*Cn;
  int er=lane>>2, ec=lane&3;
#pragma unroll
  for(int m2=0;m2<2;m2++)
#pragma unroll
  for(int nt=0;nt<8;nt++){
    int row=wm*32+m2*16+er, col=wn*64+nt*8+2*ec;
    float* av=acc[m2][nt];
    *(float2*)&Cg[(size_t)row*Cn+col]     = make_float2(av[0],av[1]);
    *(float2*)&Cg[(size_t)(row+8)*Cn+col] = make_float2(av[2],av[3]);
  }
}

__global__ void k_coef(const float* evals, const float* t, int blk){
  int b=blockIdx.x;
  const float* tb=t+blk*Cn;
  for(int idx=threadIdx.x; idx<Kn*Cn; idx+=blockDim.x){
    int k=idx>>7, c=idx&127;
    float s=0.f;
#pragma unroll
    for(int sp=0;sp<NS;sp++) s+=g_Sp[(size_t)(b*NS+sp)*Kn*Cn+idx];
    g_D[(size_t)b*Kn*Cn+idx]=expf(-evals[b*Kn+k]*fmaxf(tb[c],1e-8f))*s;
  }
}

// x = x_in @ Wf + bf  (K=16, tiny)
__global__ void k_x0(const float* xi, const float* Wf, const float* bf){
  __shared__ float w[16*128];
  __shared__ float xs[16][17];
  int tid=threadIdx.x;
  for(int i=tid;i<2048;i+=128) w[i]=Wf[i];
  int r0=blockIdx.x*16;
  for(int i=tid;i<256;i+=128) xs[i>>4][i&15]=xi[(size_t)r0*16+i];
  __syncthreads();
  float bv=bf[tid];
#pragma unroll
  for(int rr=0;rr<16;rr++){
    float s=bv;
#pragma unroll
    for(int k=0;k<16;k++) s+=xs[rr][k]*w[k*128+tid];
    g_x[(size_t)(r0+rr)*Cn+tid]=s;
  }
}

__global__ void k_tanh(){
  size_t i=(size_t)blockIdx.x*blockDim.x+threadIdx.x;
  g_gf[i]=tanhf(g_gx[i]*g_br[i]+g_gy[i]*g_bi[i]);
}

extern "C" void kernel_launch(void* const* d_in, const int* in_sizes, int n_in,
                              void* d_out, int out_size){
  const float *x_in=(const float*)d_in[0], *mass=(const float*)d_in[1],
    *evals=(const float*)d_in[2], *evecs=(const float*)d_in[3],
    *gradX=(const float*)d_in[4], *gradY=(const float*)d_in[5],
    *Wf=(const float*)d_in[6], *bf=(const float*)d_in[7],
    *Wl=(const float*)d_in[8], *bl=(const float*)d_in[9],
    *t=(const float*)d_in[10], *Are=(const float*)d_in[11], *Aim=(const float*)d_in[12],
    *W0=(const float*)d_in[13], *b0=(const float*)d_in[14],
    *W1=(const float*)d_in[15], *b1=(const float*)d_in[16],
    *W2=(const float*)d_in[17], *b2=(const float*)d_in[18];
  float* out=(float*)d_out;

  float *GXEp,*GYEp,*xp,*xdp,*gxp,*gyp,*brp,*bip,*gfp,*h0p,*h1p,*Dp;
  cudaGetSymbolAddress((void**)&GXEp,g_GXE); cudaGetSymbolAddress((void**)&GYEp,g_GYE);
  cudaGetSymbolAddress((void**)&xp,g_x);     cudaGetSymbolAddress((void**)&xdp,g_xd);
  cudaGetSymbolAddress((void**)&gxp,g_gx);   cudaGetSymbolAddress((void**)&gyp,g_gy);
  cudaGetSymbolAddress((void**)&brp,g_br);   cudaGetSymbolAddress((void**)&bip,g_bi);
  cudaGetSymbolAddress((void**)&gfp,g_gf);   cudaGetSymbolAddress((void**)&h0p,g_h0);
  cudaGetSymbolAddress((void**)&h1p,g_h1);   cudaGetSymbolAddress((void**)&Dp,g_D);

  // precompute GXE = gradX@evecs, GYE = gradY@evecs (block-invariant)
  { GArgs a{}; a.A[0][0]=gradX; a.A[1][0]=gradY; a.C[0]=GXEp; a.C[1]=GYEp;
    a.Bs[0]=evecs; a.sB[0]=(long)Vn*Kn; a.bsc[0]=1.f; a.kst[0]=Vn/16;
    a.lda=Vn; a.nseg=1; a.sA=(long)Vn*Vn; a.sC=(long)Vn*Kn; a.act=0;
    k_gemm<<<dim3(32,Bn,2),256>>>(a); }

  k_x0<<<Bn*Vn/16,128>>>(x_in,Wf,bf);

  for(int i=0;i<4;i++){
    k_spec<<<dim3(Bn,NS),256>>>(evecs,mass);
    k_coef<<<Bn,256>>>(evals,t,i);
    // x_diff = E@D, gx = GXE@D, gy = GYE@D
    { GArgs a{}; a.A[0][0]=evecs; a.A[1][0]=GXEp; a.A[2][0]=GYEp;
      a.C[0]=xdp; a.C[1]=gxp; a.C[2]=gyp;
      a.Bs[0]=Dp; a.sB[0]=(long)Kn*Cn; a.bsc[0]=1.f; a.kst[0]=Kn/16;
      a.lda=Kn; a.nseg=1; a.sA=(long)Vn*Kn; a.sC=(long)Vn*Cn; a.act=0;
      k_gemm<<<dim3(32,Bn,3),256>>>(a); }
    // br = gx@Are - gy@Aim
    { GArgs a{}; a.A[0][0]=gxp; a.A[0][1]=gyp; a.C[0]=brp;
      a.Bs[0]=Are+(size_t)i*Cn*Cn; a.sB[0]=0; a.bsc[0]= 1.f; a.kst[0]=8;
      a.Bs[1]=Aim+(size_t)i*Cn*Cn; a.sB[1]=0; a.bsc[1]=-1.f; a.kst[1]=8;
      a.lda=Cn; a.nseg=2; a.sA=(long)Vn*Cn; a.sC=(long)Vn*Cn; a.act=0;
      k_gemm<<<dim3(32,Bn,1),256>>>(a); }
    // bi = gy@Are + gx@Aim
    { GArgs a{}; a.A[0][0]=gyp; a.A[0][1]=gxp; a.C[0]=bip;
      a.Bs[0]=Are+(size_t)i*Cn*Cn; a.sB[0]=0; a.bsc[0]=1.f; a.kst[0]=8;
      a.Bs[1]=Aim+(size_t)i*Cn*Cn; a.sB[1]=0; a.bsc[1]=1.f; a.kst[1]=8;
      a.lda=Cn; a.nseg=2; a.sA=(long)Vn*Cn; a.sC=(long)Vn*Cn; a.act=0;
      k_gemm<<<dim3(32,Bn,1),256>>>(a); }
    k_tanh<<<(Bn*Vn*Cn)/256,256>>>();
    // h0 = relu([x|xd|gf] @ W0 + b0)
    { GArgs a{}; a.A[0][0]=xp; a.A[0][1]=xdp; a.A[0][2]=gfp; a.C[0]=h0p;
      const float* W=W0+(size_t)i*384*Cn;
      a.Bs[0]=W; a.Bs[1]=W+128*Cn; a.Bs[2]=W+256*Cn;
      a.sB[0]=a.sB[1]=a.sB[2]=0; a.bsc[0]=a.bsc[1]=a.bsc[2]=1.f;
      a.kst[0]=a.kst[1]=a.kst[2]=8;
      a.lda=Cn; a.nseg=3; a.sA=(long)Vn*Cn; a.sC=(long)Vn*Cn;
      a.bias=b0+(size_t)i*Cn; a.act=1;
      k_gemm<<<dim3(32,Bn,1),256>>>(a); }
    // h1 = relu(h0 @ W1 + b1)
    { GArgs a{}; a.A[0][0]=h0p; a.C[0]=h1p;
      a.Bs[0]=W1+(size_t)i*Cn*Cn; a.sB[0]=0; a.bsc[0]=1.f; a.kst[0]=8;
      a.lda=Cn; a.nseg=1; a.sA=(long)Vn*Cn; a.sC=(long)Vn*Cn;
      a.bias=b1+(size_t)i*Cn; a.act=1;
      k_gemm<<<dim3(32,Bn,1),256>>>(a); }
    // x = x + (h1 @ W2 + b2)
    { GArgs a{}; a.A[0][0]=h1p; a.C[0]=xp;
      a.Bs[0]=W2+(size_t)i*Cn*Cn; a.sB[0]=0; a.bsc[0]=1.f; a.kst[0]=8;
      a.lda=Cn; a.nseg=1; a.sA=(long)Vn*Cn; a.sC=(long)Vn*Cn;
      a.bias=b2+(size_t)i*Cn; a.res=xp; a.sRes=(long)Vn*Cn; a.act=0;
      k_gemm<<<dim3(32,Bn,1),256>>>(a); }
  }
  // out = x @ Wl + bl
  { GArgs a{}; a.A[0][0]=xp; a.C[0]=out;
    a.Bs[0]=Wl; a.sB[0]=0; a.bsc[0]=1.f; a.kst[0]=8;
    a.lda=Cn; a.nseg=1; a.sA=(long)Vn*Cn; a.sC=(long)Vn*Cn;
    a.bias=bl; a.act=0;
    k_gemm<<<dim3(32,Bn,1),256>>>(a); }
}

// round 3
// speedup vs baseline: 1.1787x; 1.1787x over previous
#include <cuda_runtime.h>

#define Bn 4
#define Vn 4096
#define Kn 128
#define Cn 128
#define NS 32
#define SA 20

// ---- scratch (allocation-free rule: __device__ globals) ----
__device__ float g_GXE[Bn*Vn*Kn], g_GYE[Bn*Vn*Kn];
__device__ float g_x[Bn*Vn*Cn], g_xd[Bn*Vn*Cn], g_gx[Bn*Vn*Cn], g_gy[Bn*Vn*Cn];
__device__ float g_br[Bn*Vn*Cn], g_bi[Bn*Vn*Cn], g_gf[Bn*Vn*Cn];
__device__ float g_h0[Bn*Vn*Cn], g_h1[Bn*Vn*Cn];
__device__ float g_Sp[Bn*NS*Kn*Cn], g_D[Bn*Kn*Cn];

__device__ __forceinline__ float tf32_hi(float x){
  unsigned u; asm("cvt.rna.tf32.f32 %0, %1;" : "=r"(u) : "f"(x));
  return __uint_as_float(u);
}
__device__ __forceinline__ void mma8(float* d, const unsigned* a, unsigned b0, unsigned b1){
  asm volatile("mma.sync.aligned.m16n8k8.row.col.f32.tf32.tf32.f32 "
               "{%0,%1,%2,%3},{%4,%5,%6,%7},{%8,%9},{%0,%1,%2,%3};"
               : "+f"(d[0]),"+f"(d[1]),"+f"(d[2]),"+f"(d[3])
               : "r"(a[0]),"r"(a[1]),"r"(a[2]),"r"(a[3]),"r"(b0),"r"(b1));
}

// ---- tile load (gmem->regs) / store (regs->smem with hi/lo split) ----
// A tile row-major [128m x 16k], row stride lda  ->  H/L[m*SA+k]
__device__ __forceinline__ void loadA(const float* A, int lda, int tid, float4* r){
#pragma unroll
  for(int i=0;i<2;i++){
    int e=tid+i*256, m=e>>2, kq=(e&3)<<2;
    r[i]=*(const float4*)(A+(size_t)m*lda+kq);
  }
}
__device__ __forceinline__ void storeA(const float4* r, int tid, float* H, float* L){
#pragma unroll
  for(int i=0;i<2;i++){
    int e=tid+i*256, m=e>>2, kq=(e&3)<<2;
    float4 v=r[i];
    float hx=tf32_hi(v.x),hy=tf32_hi(v.y),hz=tf32_hi(v.z),hw=tf32_hi(v.w);
    *(float4*)(H+m*SA+kq)=make_float4(hx,hy,hz,hw);
    *(float4*)(L+m*SA+kq)=make_float4(tf32_hi(v.x-hx),tf32_hi(v.y-hy),tf32_hi(v.z-hz),tf32_hi(v.w-hw));
  }
}
// source row-major [16k x 128n], row stride ldb, stored TRANSPOSED -> H/L[n*SA+k]
__device__ __forceinline__ void loadT(const float* Bg, int ldb, int tid, float4* r){
#pragma unroll
  for(int i=0;i<2;i++){
    int e=tid+i*256, k=e&15, nq=(e>>4)<<2;
    r[i]=*(const float4*)(Bg+(size_t)k*ldb+nq);
  }
}
__device__ __forceinline__ void storeT(const float4* r, const float* sc2, float sc,
                                       int tid, float* H, float* L){
#pragma unroll
  for(int i=0;i<2;i++){
    int e=tid+i*256, k=e&15, nq=(e>>4)<<2;
    float s = sc2 ? sc*sc2[i] : sc;
    float4 v=r[i];
    float ax=v.x*s, ay=v.y*s, az=v.z*s, aw=v.w*s;
    float hx=tf32_hi(ax),hy=tf32_hi(ay),hz=tf32_hi(az),hw=tf32_hi(aw);
    H[(nq+0)*SA+k]=hx; L[(nq+0)*SA+k]=tf32_hi(ax-hx);
    H[(nq+1)*SA+k]=hy; L[(nq+1)*SA+k]=tf32_hi(ay-hy);
    H[(nq+2)*SA+k]=hz; L[(nq+2)*SA+k]=tf32_hi(az-hz);
    H[(nq+3)*SA+k]=hw; L[(nq+3)*SA+k]=tf32_hi(aw-hw);
  }
}

// one 16-deep K step, 3xTF32, warp tile 32x64 (8 warps -> 128x128)
__device__ __forceinline__ void gstep(const float* Ah,const float* Al,
                                      const float* Bh,const float* Bl,
                                      float (&acc)[2][8][4], int wm,int wn,int lane){
  int r=lane>>2, c=lane&3;
#pragma unroll
  for(int ks=0;ks<16;ks+=8){
    unsigned ah[2][4], al[2][4];
#pragma unroll
    for(int mt=0;mt<2;mt++){
      const float* p=Ah+(wm*32+mt*16+r)*SA+ks+c;
      ah[mt][0]=__float_as_uint(p[0]); ah[mt][1]=__float_as_uint(p[8*SA]);
      ah[mt][2]=__float_as_uint(p[4]); ah[mt][3]=__float_as_uint(p[8*SA+4]);
      const float* q=Al+(wm*32+mt*16+r)*SA+ks+c;
      al[mt][0]=__float_as_uint(q[0]); al[mt][1]=__float_as_uint(q[8*SA]);
      al[mt][2]=__float_as_uint(q[4]); al[mt][3]=__float_as_uint(q[8*SA+4]);
    }
#pragma unroll
    for(int nt=0;nt<8;nt++){
      const float* p=Bh+(wn*64+nt*8+r)*SA+ks+c;
      unsigned bh0=__float_as_uint(p[0]), bh1=__float_as_uint(p[4]);
      const float* q=Bl+(wn*64+nt*8+r)*SA+ks+c;
      unsigned bl0=__float_as_uint(q[0]), bl1=__float_as_uint(q[4]);
#pragma unroll
      for(int mt=0;mt<2;mt++){
        mma8(acc[mt][nt],ah[mt],bh0,bh1);
        mma8(acc[mt][nt],ah[mt],bl0,bl1);
        mma8(acc[mt][nt],al[mt],bh0,bh1);
      }
    }
  }
}

struct GArgs {
  const float* A[3][3];   // [z][seg]
  float* C[3];            // [z]
  const float* Bs[3]; long sB[3]; int kst[3];
  float bscz[3][3];       // [z][seg]
  int lda, nseg;
  long sA, sC;
  const float* bias; const float* res; long sRes;
  int act;                // 1 = relu
};

__global__ void __launch_bounds__(256) k_gemm(GArgs ga){
  __shared__ float Ah[128*SA],Al[128*SA],Bh[128*SA],Bl[128*SA];
  int tid=threadIdx.x, lane=tid&31, w=tid>>5, wm=w&3, wn=w>>2;
  float acc[2][8][4]={};
  int mt=blockIdx.x, b=blockIdx.y, z=blockIdx.z;
  int tot=0;
#pragma unroll
  for(int s=0;s<3;s++) if(s<ga.nseg) tot+=ga.kst[s];
  int seg=0,k0=0;
  const float* As   = ga.A[z][0] + (size_t)b*ga.sA + (size_t)mt*128*ga.lda;
  const float* Bsrc = ga.Bs[0]   + (size_t)b*ga.sB[0];
  float sc = ga.bscz[z][0];
  float4 ra[2], rb[2];
  loadA(As, ga.lda, tid, ra);
  loadT(Bsrc, 128, tid, rb);
  for(int s=0;s<tot;s++){
    storeA(ra, tid, Ah, Al);
    storeT(rb, nullptr, sc, tid, Bh, Bl);
    __syncthreads();
    if(s+1<tot){
      k0++;
      if(k0==ga.kst[seg]){
        k0=0; seg++;
        As   = ga.A[z][seg] + (size_t)b*ga.sA + (size_t)mt*128*ga.lda;
        Bsrc = ga.Bs[seg]   + (size_t)b*ga.sB[seg];
        sc = ga.bscz[z][seg];
      }
      loadA(As + k0*16, ga.lda, tid, ra);
      loadT(Bsrc + (size_t)k0*16*128, 128, tid, rb);
    }
    gstep(Ah,Al,Bh,Bl,acc,wm,wn,lane);
    __syncthreads();
  }
  float* Cg = ga.C[z] + (size_t)b*ga.sC + (size_t)mt*128*Cn;
  const float* Rg = ga.res ? ga.res + (size_t)b*ga.sRes + (size_t)mt*128*Cn : nullptr;
  int er=lane>>2, ec=lane&3;
#pragma unroll
  for(int m2=0;m2<2;m2++)
#pragma unroll
  for(int nt=0;nt<8;nt++){
    int row=wm*32+m2*16+er, col=wn*64+nt*8+2*ec;
    float* av=acc[m2][nt];
#pragma unroll
    for(int rr=0;rr<2;rr++){
      int R=row+rr*8;
      float v0=av[rr*2], v1=av[rr*2+1];
      if(ga.bias){ v0+=ga.bias[col]; v1+=ga.bias[col+1]; }
      if(ga.act==1){ v0=fmaxf(v0,0.f); v1=fmaxf(v1,0.f); }
      if(Rg){ v0+=Rg[(size_t)R*Cn+col]; v1+=Rg[(size_t)R*Cn+col+1]; }
      Cg[(size_t)R*Cn+col]=v0; Cg[(size_t)R*Cn+col+1]=v1;
    }
  }
}

// x_spec split-K partials: Sp[b,sp] = E[v0:v0+V/NS]^T @ (x*mass)[v0:v0+V/NS]
__global__ void __launch_bounds__(256) k_spec(const float* E, const float* mass){
  __shared__ float Ah[128*SA],Al[128*SA],Bh[128*SA],Bl[128*SA];
  int tid=threadIdx.x, lane=tid&31, w=tid>>5, wm=w&3, wn=w>>2;
  float acc[2][8][4]={};
  int b=blockIdx.x, sp=blockIdx.y;
  const float* Eb=E+(size_t)b*Vn*Kn;
  const float* Xb=g_x+(size_t)b*Vn*Cn;
  const float* Mb=mass+(size_t)b*Vn;
  int v0=sp*(Vn/NS);
  const int steps=(Vn/NS)/16;
  float4 ra[2], rb[2]; float ms[2];
  loadT(Eb+(size_t)v0*Kn, Kn, tid, ra);
  loadT(Xb+(size_t)v0*Cn, Cn, tid, rb);
#pragma unroll
  for(int i=0;i<2;i++){ int e=tid+i*256; ms[i]=Mb[v0+(e&15)]; }
  for(int s=0;s<steps;s++){
    storeA:;
    storeT(ra, nullptr, 1.f, tid, Ah, Al);
    storeT(rb, ms, 1.f, tid, Bh, Bl);
    __syncthreads();
    if(s+1<steps){
      int v=v0+(s+1)*16;
      loadT(Eb+(size_t)v*Kn, Kn, tid, ra);
      loadT(Xb+(size_t)v*Cn, Cn, tid, rb);
#pragma unroll
      for(int i=0;i<2;i++){ int e=tid+i*256; ms[i]=Mb[v+(e&15)]; }
    }
    gstep(Ah,Al,Bh,Bl,acc,wm,wn,lane);
    __syncthreads();
  }
  float* Cg=g_Sp+(size_t)(b*NS+sp)*Kn*Cn;
  int er=lane>>2, ec=lane&3;
#pragma unroll
  for(int m2=0;m2<2;m2++)
#pragma unroll
  for(int nt=0;nt<8;nt++){
    int row=wm*32+m2*16+er, col=wn*64+nt*8+2*ec;
    float* av=acc[m2][nt];
    *(float2*)&Cg[(size_t)row*Cn+col]     = make_float2(av[0],av[1]);
    *(float2*)&Cg[(size_t)(row+8)*Cn+col] = make_float2(av[2],av[3]);
  }
}

// reduce NS split partials + apply diffusion coefficients (wide grid)
__global__ void k_coef(const float* evals, const float* t, int blk){
  int b=blockIdx.x;
  int base=blockIdx.y*1024;
  const float* tb=t+blk*Cn;
  for(int i=threadIdx.x; i<1024; i+=blockDim.x){
    int idx=base+i;
    int k=idx>>7, c=idx&127;
    float s=0.f;
#pragma unroll
    for(int sp=0;sp<NS;sp++) s+=g_Sp[(size_t)(b*NS+sp)*Kn*Cn+idx];
    g_D[(size_t)b*Kn*Cn+idx]=expf(-evals[b*Kn+k]*fmaxf(tb[c],1e-8f))*s;
  }
}

// x = x_in @ Wf + bf  (K=16, tiny)
__global__ void k_x0(const float* xi, const float* Wf, const float* bf){
  __shared__ float w[16*128];
  __shared__ float xs[16][17];
  int tid=threadIdx.x;
  for(int i=tid;i<2048;i+=128) w[i]=Wf[i];
  int r0=blockIdx.x*16;
  for(int i=tid;i<256;i+=128) xs[i>>4][i&15]=xi[(size_t)r0*16+i];
  __syncthreads();
  float bv=bf[tid];
#pragma unroll
  for(int rr=0;rr<16;rr++){
    float s=bv;
#pragma unroll
    for(int k=0;k<16;k++) s+=xs[rr][k]*w[k*128+tid];
    g_x[(size_t)(r0+rr)*Cn+tid]=s;
  }
}

__global__ void k_tanh(){
  size_t i=(size_t)blockIdx.x*blockDim.x+threadIdx.x;
  g_gf[i]=tanhf(g_gx[i]*g_br[i]+g_gy[i]*g_bi[i]);
}

extern "C" void kernel_launch(void* const* d_in, const int* in_sizes, int n_in,
                              void* d_out, int out_size){
  const float *x_in=(const float*)d_in[0], *mass=(const float*)d_in[1],
    *evals=(const float*)d_in[2], *evecs=(const float*)d_in[3],
    *gradX=(const float*)d_in[4], *gradY=(const float*)d_in[5],
    *Wf=(const float*)d_in[6], *bf=(const float*)d_in[7],
    *Wl=(const float*)d_in[8], *bl=(const float*)d_in[9],
    *t=(const float*)d_in[10], *Are=(const float*)d_in[11], *Aim=(const float*)d_in[12],
    *W0=(const float*)d_in[13], *b0=(const float*)d_in[14],
    *W1=(const float*)d_in[15], *b1=(const float*)d_in[16],
    *W2=(const float*)d_in[17], *b2=(const float*)d_in[18];
  float* out=(float*)d_out;

  float *GXEp,*GYEp,*xp,*xdp,*gxp,*gyp,*brp,*bip,*gfp,*h0p,*h1p,*Dp;
  cudaGetSymbolAddress((void**)&GXEp,g_GXE); cudaGetSymbolAddress((void**)&GYEp,g_GYE);
  cudaGetSymbolAddress((void**)&xp,g_x);     cudaGetSymbolAddress((void**)&xdp,g_xd);
  cudaGetSymbolAddress((void**)&gxp,g_gx);   cudaGetSymbolAddress((void**)&gyp,g_gy);
  cudaGetSymbolAddress((void**)&brp,g_br);   cudaGetSymbolAddress((void**)&bip,g_bi);
  cudaGetSymbolAddress((void**)&gfp,g_gf);   cudaGetSymbolAddress((void**)&h0p,g_h0);
  cudaGetSymbolAddress((void**)&h1p,g_h1);   cudaGetSymbolAddress((void**)&Dp,g_D);

  // precompute GXE = gradX@evecs, GYE = gradY@evecs (block-invariant)
  { GArgs a{}; a.A[0][0]=gradX; a.A[1][0]=gradY; a.C[0]=GXEp; a.C[1]=GYEp;
    a.Bs[0]=evecs; a.sB[0]=(long)Vn*Kn; a.bscz[0][0]=1.f; a.bscz[1][0]=1.f;
    a.kst[0]=Vn/16; a.lda=Vn; a.nseg=1; a.sA=(long)Vn*Vn; a.sC=(long)Vn*Kn; a.act=0;
    k_gemm<<<dim3(32,Bn,2),256>>>(a); }

  k_x0<<<Bn*Vn/16,128>>>(x_in,Wf,bf);

  for(int i=0;i<4;i++){
    k_spec<<<dim3(Bn,NS),256>>>(evecs,mass);
    k_coef<<<dim3(Bn,16),256>>>(evals,t,i);
    // x_diff = E@D, gx = GXE@D, gy = GYE@D
    { GArgs a{}; a.A[0][0]=evecs; a.A[1][0]=GXEp; a.A[2][0]=GYEp;
      a.C[0]=xdp; a.C[1]=gxp; a.C[2]=gyp;
      a.Bs[0]=Dp; a.sB[0]=(long)Kn*Cn;
      a.bscz[0][0]=1.f; a.bscz[1][0]=1.f; a.bscz[2][0]=1.f;
      a.kst[0]=Kn/16; a.lda=Kn; a.nseg=1; a.sA=(long)Vn*Kn; a.sC=(long)Vn*Cn; a.act=0;
      k_gemm<<<dim3(32,Bn,3),256>>>(a); }
    // br = gx@Are - gy@Aim ; bi = gy@Are + gx@Aim  (one launch, z=2)
    { GArgs a{}; a.A[0][0]=gxp; a.A[0][1]=gyp; a.A[1][0]=gyp; a.A[1][1]=gxp;
      a.C[0]=brp; a.C[1]=bip;
      a.Bs[0]=Are+(size_t)i*Cn*Cn; a.sB[0]=0;
      a.Bs[1]=Aim+(size_t)i*Cn*Cn; a.sB[1]=0;
      a.bscz[0][0]=1.f; a.bscz[0][1]=-1.f;
      a.bscz[1][0]=1.f; a.bscz[1][1]= 1.f;
      a.kst[0]=8; a.kst[1]=8;
      a.lda=Cn; a.nseg=2; a.sA=(long)Vn*Cn; a.sC=(long)Vn*Cn; a.act=0;
      k_gemm<<<dim3(32,Bn,2),256>>>(a); }
    k_tanh<<<(Bn*Vn*Cn)/256,256>>>();
    // h0 = relu([x|xd|gf] @ W0 + b0)
    { GArgs a{}; a.A[0][0]=xp; a.A[0][1]=xdp; a.A[0][2]=gfp; a.C[0]=h0p;
      const float* W=W0+(size_t)i*384*Cn;
      a.Bs[0]=W; a.Bs[1]=W+128*Cn; a.Bs[2]=W+256*Cn;
      a.sB[0]=a.sB[1]=a.sB[2]=0;
      a.bscz[0][0]=a.bscz[0][1]=a.bscz[0][2]=1.f;
      a.kst[0]=a.kst[1]=a.kst[2]=8;
      a.lda=Cn; a.nseg=3; a.sA=(long)Vn*Cn; a.sC=(long)Vn*Cn;
      a.bias=b0+(size_t)i*Cn; a.act=1;
      k_gemm<<<dim3(32,Bn,1),256>>>(a); }
    // h1 = relu(h0 @ W1 + b1)
    { GArgs a{}; a.A[0][0]=h0p; a.C[0]=h1p;
      a.Bs[0]=W1+(size_t)i*Cn*Cn; a.sB[0]=0; a.bscz[0][0]=1.f; a.kst[0]=8;
      a.lda=Cn; a.nseg=1; a.sA=(long)Vn*Cn; a.sC=(long)Vn*Cn;
      a.bias=b1+(size_t)i*Cn; a.act=1;
      k_gemm<<<dim3(32,Bn,1),256>>>(a); }
    // x = x + (h1 @ W2 + b2)
    { GArgs a{}; a.A[0][0]=h1p; a.C[0]=xp;
      a.Bs[0]=W2+(size_t)i*Cn*Cn; a.sB[0]=0; a.bscz[0][0]=1.f; a.kst[0]=8;
      a.lda=Cn; a.nseg=1; a.sA=(long)Vn*Cn; a.sC=(long)Vn*Cn;
      a.bias=b2+(size_t)i*Cn; a.res=xp; a.sRes=(long)Vn*Cn; a.act=0;
      k_gemm<<<dim3(32,Bn,1),256>>>(a); }
  }
  // out = x @ Wl + bl
  { GArgs a{}; a.A[0][0]=xp; a.C[0]=out;
    a.Bs[0]=Wl; a.sB[0]=0; a.bscz[0][0]=1.f; a.kst[0]=8;
    a.lda=Cn; a.nseg=1; a.sA=(long)Vn*Cn; a.sC=(long)Vn*Cn;
    a.bias=bl; a.act=0;
    k_gemm<<<dim3(32,Bn,1),256>>>(a); }
}

// round 9
// speedup vs baseline: 2.0642x; 1.7512x over previous
#include <cuda_runtime.h>
#include <cuda_fp16.h>
#include <cstdint>

#define Bn 4
#define Vn 4096
#define Kn 128
#define Cn 128
#define NS 32

// ---- scratch (allocation-free rule: __device__ globals) ----
__device__ float g_GXE[Bn*Vn*Kn], g_GYE[Bn*Vn*Kn];
__device__ float g_x[Bn*Vn*Cn], g_xd[Bn*Vn*Cn], g_gx[Bn*Vn*Cn], g_gy[Bn*Vn*Cn];
__device__ float g_br[Bn*Vn*Cn], g_bi[Bn*Vn*Cn], g_gf[Bn*Vn*Cn];
__device__ float g_h0[Bn*Vn*Cn], g_h1[Bn*Vn*Cn];
__device__ float g_Sp[Bn*NS*Kn*Cn], g_D[Bn*Kn*Cn];

// A tiles: [128 m][16 k] halves, row stride 48B (32B data + 16B pad) -> conflict-free ldmatrix
// B tiles: [16 k][128 n] halves, row stride 272B (256B data + 16B pad)
#define SA_B 48
#define SB_B 272

__device__ __forceinline__ uint32_t s2u(const void* p){
  uint32_t a; asm("{ .reg .u64 t; cvta.to.shared.u64 t, %1; cvt.u32.u64 %0, t; }":"=r"(a):"l"(p));
  return a;
}
__device__ __forceinline__ uint32_t packh(__half a, __half b){
  __half2 t=__halves2half2(a,b); return *(uint32_t*)&t;
}
__device__ __forceinline__ void split2(float x, __half& h, __half& l){
  h=__float2half_rn(x); l=__float2half_rn(x-__half2float(h));
}
__device__ __forceinline__ void ldsm4(uint32_t a, uint32_t* r){
  asm volatile("ldmatrix.sync.aligned.m8n8.x4.shared.b16 {%0,%1,%2,%3},[%4];"
    :"=r"(r[0]),"=r"(r[1]),"=r"(r[2]),"=r"(r[3]):"r"(a));
}
__device__ __forceinline__ void ldsm4t(uint32_t a, uint32_t* r){
  asm volatile("ldmatrix.sync.aligned.m8n8.x4.trans.shared.b16 {%0,%1,%2,%3},[%4];"
    :"=r"(r[0]),"=r"(r[1]),"=r"(r[2]),"=r"(r[3]):"r"(a));
}
__device__ __forceinline__ void mma16(float* d, const uint32_t* a, uint32_t b0, uint32_t b1){
  asm volatile("mma.sync.aligned.m16n8k16.row.col.f32.f16.f16.f32 "
    "{%0,%1,%2,%3},{%4,%5,%6,%7},{%8,%9},{%0,%1,%2,%3};"
    : "+f"(d[0]),"+f"(d[1]),"+f"(d[2]),"+f"(d[3])
    : "r"(a[0]),"r"(a[1]),"r"(a[2]),"r"(a[3]),"r"(b0),"r"(b1));
}

// ---- gmem->regs prefetch ----
__device__ __forceinline__ void ldA(const float* A, int lda, int tid, float4* r){
#pragma unroll
  for(int i=0;i<2;i++){ int idx=tid+i*256;
    r[i]=*(const float4*)(A+(size_t)(idx>>2)*lda+((idx&3)<<2)); }
}
__device__ __forceinline__ void ldB(const float* S, int lds, int tid, float4* r){
#pragma unroll
  for(int i=0;i<2;i++){ int idx=tid+i*256;
    r[i]=*(const float4*)(S+(size_t)(idx&15)*lds+(((idx>>4)&31)<<2)); }
}
// ---- regs->smem staging with fp16 hi/lo split ----
__device__ __forceinline__ void stA(char* H, char* L, const float4* r, int tid){
#pragma unroll
  for(int i=0;i<2;i++){
    int idx=tid+i*256; int m=idx>>2, kq=(idx&3)<<2;
    float4 v=r[i];
    __half h0,h1,h2,h3,l0,l1,l2,l3;
    split2(v.x,h0,l0); split2(v.y,h1,l1); split2(v.z,h2,l2); split2(v.w,h3,l3);
    *(uint2*)(H+m*SA_B+kq*2)=make_uint2(packh(h0,h1),packh(h2,h3));
    *(uint2*)(L+m*SA_B+kq*2)=make_uint2(packh(l0,l1),packh(l2,l3));
  }
}
__device__ __forceinline__ void stB(char* H, char* L, const float4* r, int tid,
                                    const float* si){
#pragma unroll
  for(int i=0;i<2;i++){
    int idx=tid+i*256; int k=idx&15, nq=((idx>>4)&31)<<2;
    float s=si[i];
    float4 v=r[i];
    __half h0,h1,h2,h3,l0,l1,l2,l3;
    split2(v.x*s,h0,l0); split2(v.y*s,h1,l1); split2(v.z*s,h2,l2); split2(v.w*s,h3,l3);
    *(uint2*)(H+k*SB_B+nq*2)=make_uint2(packh(h0,h1),packh(h2,h3));
    *(uint2*)(L+k*SB_B+nq*2)=make_uint2(packh(l0,l1),packh(l2,l3));
  }
}
// transposed A staging (for k_spec: A = E^T): source [16 k][128 m] -> A layout [m][k]
__device__ __forceinline__ void stTA(char* H, char* L, const float4* r, int tid){
#pragma unroll
  for(int i=0;i<2;i++){
    int idx=tid+i*256; int k=idx&15, nq=((idx>>4)&31)<<2;
    float4 v=r[i];
    float e[4]={v.x,v.y,v.z,v.w};
#pragma unroll
    for(int j=0;j<4;j++){
      __half h,l; split2(e[j],h,l);
      *(__half*)(H+(nq+j)*SA_B+k*2)=h;
      *(__half*)(L+(nq+j)*SA_B+k*2)=l;
    }
  }
}

// one 16-deep K step: double-fp16 (3 mma / k16), warp tile 32x64, 8 warps -> 128x128
__device__ __forceinline__ void gstep(uint32_t aH, uint32_t aL, uint32_t bH, uint32_t bL,
                                      float (&acc)[2][8][4], int wm,int wn,int lane){
  int lr=lane&15, lc=lane>>4;
  uint32_t ah[2][4], al[2][4];
#pragma unroll
  for(int mt=0;mt<2;mt++){
    uint32_t off=(uint32_t)((wm*32+mt*16+lr)*SA_B+lc*16);
    ldsm4(aH+off, ah[mt]); ldsm4(aL+off, al[mt]);
  }
#pragma unroll
  for(int bt=0;bt<4;bt++){
    uint32_t bh[4], bl[4];
    uint32_t off=(uint32_t)(lr*SB_B+(wn*64+bt*16+lc*8)*2);
    ldsm4t(bH+off, bh); ldsm4t(bL+off, bl);
#pragma unroll
    for(int j=0;j<2;j++){
      int nt=bt*2+j;
#pragma unroll
      for(int mt=0;mt<2;mt++){
        mma16(acc[mt][nt], ah[mt], bh[2*j], bh[2*j+1]);
        mma16(acc[mt][nt], ah[mt], bl[2*j], bl[2*j+1]);
        mma16(acc[mt][nt], al[mt], bh[2*j], bh[2*j+1]);
      }
    }
  }
}

struct GArgs {
  const float* A[3][3];   // [z][seg]
  float* C[3];            // [z]
  const float* Bs[3]; long sB[3]; int kst[3];  // kst in 16-wide tiles
  float bscz[3][3];       // [z][seg]
  int lda, nseg;
  long sA, sC;
  const float* bias; const float* res; long sRes;
  int act;                // 1 = relu
};

__global__ void __launch_bounds__(256) k_gemm(GArgs ga){
  __shared__ __align__(16) char AhB[128*SA_B], AlB[128*SA_B];
  __shared__ __align__(16) char BhB[16*SB_B],  BlB[16*SB_B];
  int tid=threadIdx.x, lane=tid&31, w=tid>>5, wm=w&3, wn=w>>2;
  uint32_t aH=s2u(AhB), aL=s2u(AlB), bH=s2u(BhB), bL=s2u(BlB);
  float acc[2][8][4]={};
  int mt=blockIdx.x, b=blockIdx.y, z=blockIdx.z;
  int T=0;
#pragma unroll
  for(int s=0;s<3;s++) if(s<ga.nseg) T+=ga.kst[s];
  int seg=0,k0=0;
  const float* As   = ga.A[z][0] + (size_t)b*ga.sA + (size_t)mt*128*ga.lda;
  const float* Bsrc = ga.Bs[0]   + (size_t)b*ga.sB[0];
  float sc = ga.bscz[z][0];
  float4 ra[2], rb[2]; float si[2];
  ldA(As, ga.lda, tid, ra);
  ldB(Bsrc, Cn, tid, rb);
  si[0]=si[1]=sc;
  for(int s=0;s<T;s++){
    stA(AhB, AlB, ra, tid);
    stB(BhB, BlB, rb, tid, si);
    __syncthreads();
    if(s+1<T){
      k0++;
      if(k0==ga.kst[seg]){
        k0=0; seg++;
        As   = ga.A[z][seg] + (size_t)b*ga.sA + (size_t)mt*128*ga.lda;
        Bsrc = ga.Bs[seg]   + (size_t)b*ga.sB[seg];
        sc = ga.bscz[z][seg];
      }
      ldA(As + k0*16, ga.lda, tid, ra);
      ldB(Bsrc + (size_t)k0*16*Cn, Cn, tid, rb);
      si[0]=si[1]=sc;
    }
    gstep(aH,aL,bH,bL,acc,wm,wn,lane);
    __syncthreads();
  }
  float* Cg = ga.C[z] + (size_t)b*ga.sC + (size_t)mt*128*Cn;
  const float* Rg = ga.res ? ga.res + (size_t)b*ga.sRes + (size_t)mt*128*Cn : nullptr;
  int er=lane>>2, ec=lane&3;
#pragma unroll
  for(int m2=0;m2<2;m2++)
#pragma unroll
  for(int nt=0;nt<8;nt++){
    int row=wm*32+m2*16+er, col=wn*64+nt*8+2*ec;
    float* av=acc[m2][nt];
#pragma unroll
    for(int rr=0;rr<2;rr++){
      int R=row+rr*8;
      float v0=av[rr*2], v1=av[rr*2+1];
      if(ga.bias){ v0+=ga.bias[col]; v1+=ga.bias[col+1]; }
      if(ga.act==1){ v0=fmaxf(v0,0.f); v1=fmaxf(v1,0.f); }
      if(Rg){ v0+=Rg[(size_t)R*Cn+col]; v1+=Rg[(size_t)R*Cn+col+1]; }
      Cg[(size_t)R*Cn+col]=v0; Cg[(size_t)R*Cn+col+1]=v1;
    }
  }
}

// x_spec split-K partials: Sp[b,sp] = E[v0:v0+V/NS]^T @ (x*mass)[v0:v0+V/NS]
__global__ void __launch_bounds__(256) k_spec(const float* E, const float* mass){
  __shared__ __align__(16) char AhB[128*SA_B], AlB[128*SA_B];
  __shared__ __align__(16) char BhB[16*SB_B],  BlB[16*SB_B];
  int tid=threadIdx.x, lane=tid&31, w=tid>>5, wm=w&3, wn=w>>2;
  uint32_t aH=s2u(AhB), aL=s2u(AlB), bH=s2u(BhB), bL=s2u(BlB);
  float acc[2][8][4]={};
  int b=blockIdx.x, sp=blockIdx.y;
  const float* Eb=E+(size_t)b*Vn*Kn;
  const float* Xb=g_x+(size_t)b*Vn*Cn;
  const float* Mb=mass+(size_t)b*Vn;
  int v0=sp*(Vn/NS);
  const int T=(Vn/NS)/16;
  float4 ra[2], rb[2]; float ms[2];
  ldB(Eb+(size_t)v0*Kn, Kn, tid, ra);   // E rows are k-dim here
  ldB(Xb+(size_t)v0*Cn, Cn, tid, rb);
#pragma unroll
  for(int i=0;i<2;i++){ int idx=tid+i*256; ms[i]=Mb[v0+(idx&15)]; }
  for(int s=0;s<T;s++){
    stTA(AhB, AlB, ra, tid);
    stB(BhB, BlB, rb, tid, ms);
    __syncthreads();
    if(s+1<T){
      int v=v0+(s+1)*16;
      ldB(Eb+(size_t)v*Kn, Kn, tid, ra);
      ldB(Xb+(size_t)v*Cn, Cn, tid, rb);
#pragma unroll
      for(int i=0;i<2;i++){ int idx=tid+i*256; ms[i]=Mb[v+(idx&15)]; }
    }
    gstep(aH,aL,bH,bL,acc,wm,wn,lane);
    __syncthreads();
  }
  float* Cg=g_Sp+(size_t)(b*NS+sp)*Kn*Cn;
  int er=lane>>2, ec=lane&3;
#pragma unroll
  for(int m2=0;m2<2;m2++)
#pragma unroll
  for(int nt=0;nt<8;nt++){
    int row=wm*32+m2*16+er, col=wn*64+nt*8+2*ec;
    float* av=acc[m2][nt];
    *(float2*)&Cg[(size_t)row*Cn+col]     = make_float2(av[0],av[1]);
    *(float2*)&Cg[(size_t)(row+8)*Cn+col] = make_float2(av[2],av[3]);
  }
}

// reduce NS split partials + apply diffusion coefficients
__global__ void k_coef(const float* evals, const float* t, int blk){
  int b=blockIdx.x;
  int base=blockIdx.y*1024;
  const float* tb=t+blk*Cn;
  for(int i=threadIdx.x; i<1024; i+=blockDim.x){
    int idx=base+i;
    int k=idx>>7, c=idx&127;
    float s=0.f;
#pragma unroll
    for(int sp=0;sp<NS;sp++) s+=g_Sp[(size_t)(b*NS+sp)*Kn*Cn+idx];
    g_D[(size_t)b*Kn*Cn+idx]=expf(-evals[b*Kn+k]*fmaxf(tb[c],1e-8f))*s;
  }
}

// x = x_in @ Wf + bf  (K=16, tiny)
__global__ void k_x0(const float* xi, const float* Wf, const float* bf){
  __shared__ float w[16*128];
  __shared__ float xs[16][17];
  int tid=threadIdx.x;
  for(int i=tid;i<2048;i+=128) w[i]=Wf[i];
  int r0=blockIdx.x*16;
  for(int i=tid;i<256;i+=128) xs[i>>4][i&15]=xi[(size_t)r0*16+i];
  __syncthreads();
  float bv=bf[tid];
#pragma unroll
  for(int rr=0;rr<16;rr++){
    float s=bv;
#pragma unroll
    for(int k=0;k<16;k++) s+=xs[rr][k]*w[k*128+tid];
    g_x[(size_t)(r0+rr)*Cn+tid]=s;
  }
}

__global__ void k_tanh(){
  size_t i=(size_t)blockIdx.x*blockDim.x+threadIdx.x;
  g_gf[i]=tanhf(g_gx[i]*g_br[i]+g_gy[i]*g_bi[i]);
}

extern "C" void kernel_launch(void* const* d_in, const int* in_sizes, int n_in,
                              void* d_out, int out_size){
  const float *x_in=(const float*)d_in[0], *mass=(const float*)d_in[1],
    *evals=(const float*)d_in[2], *evecs=(const float*)d_in[3],
    *gradX=(const float*)d_in[4], *gradY=(const float*)d_in[5],
    *Wf=(const float*)d_in[6], *bf=(const float*)d_in[7],
    *Wl=(const float*)d_in[8], *bl=(const float*)d_in[9],
    *t=(const float*)d_in[10], *Are=(const float*)d_in[11], *Aim=(const float*)d_in[12],
    *W0=(const float*)d_in[13], *b0=(const float*)d_in[14],
    *W1=(const float*)d_in[15], *b1=(const float*)d_in[16],
    *W2=(const float*)d_in[17], *b2=(const float*)d_in[18];
  float* out=(float*)d_out;

  float *GXEp,*GYEp,*xp,*xdp,*gxp,*gyp,*brp,*bip,*gfp,*h0p,*h1p,*Dp;
  cudaGetSymbolAddress((void**)&GXEp,g_GXE); cudaGetSymbolAddress((void**)&GYEp,g_GYE);
  cudaGetSymbolAddress((void**)&xp,g_x);     cudaGetSymbolAddress((void**)&xdp,g_xd);
  cudaGetSymbolAddress((void**)&gxp,g_gx);   cudaGetSymbolAddress((void**)&gyp,g_gy);
  cudaGetSymbolAddress((void**)&brp,g_br);   cudaGetSymbolAddress((void**)&bip,g_bi);
  cudaGetSymbolAddress((void**)&gfp,g_gf);   cudaGetSymbolAddress((void**)&h0p,g_h0);
  cudaGetSymbolAddress((void**)&h1p,g_h1);   cudaGetSymbolAddress((void**)&Dp,g_D);

  // precompute GXE = gradX@evecs, GYE = gradY@evecs (block-invariant)
  { GArgs a{}; a.A[0][0]=gradX; a.A[1][0]=gradY; a.C[0]=GXEp; a.C[1]=GYEp;
    a.Bs[0]=evecs; a.sB[0]=(long)Vn*Kn; a.bscz[0][0]=1.f; a.bscz[1][0]=1.f;
    a.kst[0]=Vn/16; a.lda=Vn; a.nseg=1; a.sA=(long)Vn*Vn; a.sC=(long)Vn*Kn; a.act=0;
    k_gemm<<<dim3(32,Bn,2),256>>>(a); }

  k_x0<<<Bn*Vn/16,128>>>(x_in,Wf,bf);

  for(int i=0;i<4;i++){
    k_spec<<<dim3(Bn,NS),256>>>(evecs,mass);
    k_coef<<<dim3(Bn,16),256>>>(evals,t,i);
    // x_diff = E@D, gx = GXE@D, gy = GYE@D
    { GArgs a{}; a.A[0][0]=evecs; a.A[1][0]=GXEp; a.A[2][0]=GYEp;
      a.C[0]=xdp; a.C[1]=gxp; a.C[2]=gyp;
      a.Bs[0]=Dp; a.sB[0]=(long)Kn*Cn;
      a.bscz[0][0]=1.f; a.bscz[1][0]=1.f; a.bscz[2][0]=1.f;
      a.kst[0]=Kn/16; a.lda=Kn; a.nseg=1; a.sA=(long)Vn*Kn; a.sC=(long)Vn*Cn; a.act=0;
      k_gemm<<<dim3(32,Bn,3),256>>>(a); }
    // br = gx@Are - gy@Aim ; bi = gy@Are + gx@Aim  (one launch, z=2)
    { GArgs a{}; a.A[0][0]=gxp; a.A[0][1]=gyp; a.A[1][0]=gyp; a.A[1][1]=gxp;
      a.C[0]=brp; a.C[1]=bip;
      a.Bs[0]=Are+(size_t)i*Cn*Cn; a.sB[0]=0;
      a.Bs[1]=Aim+(size_t)i*Cn*Cn; a.sB[1]=0;
      a.bscz[0][0]=1.f; a.bscz[0][1]=-1.f;
      a.bscz[1][0]=1.f; a.bscz[1][1]= 1.f;
      a.kst[0]=Kn/16; a.kst[1]=Kn/16;
      a.lda=Cn; a.nseg=2; a.sA=(long)Vn*Cn; a.sC=(long)Vn*Cn; a.act=0;
      k_gemm<<<dim3(32,Bn,2),256>>>(a); }
    k_tanh<<<(Bn*Vn*Cn)/256,256>>>();
    // h0 = relu([x|xd|gf] @ W0 + b0)
    { GArgs a{}; a.A[0][0]=xp; a.A[0][1]=xdp; a.A[0][2]=gfp; a.C[0]=h0p;
      const float* W=W0+(size_t)i*384*Cn;
      a.Bs[0]=W; a.Bs[1]=W+128*Cn; a.Bs[2]=W+256*Cn;
      a.sB[0]=a.sB[1]=a.sB[2]=0;
      a.bscz[0][0]=a.bscz[0][1]=a.bscz[0][2]=1.f;
      a.kst[0]=a.kst[1]=a.kst[2]=Kn/16;
      a.lda=Cn; a.nseg=3; a.sA=(long)Vn*Cn; a.sC=(long)Vn*Cn;
      a.bias=b0+(size_t)i*Cn; a.act=1;
      k_gemm<<<dim3(32,Bn,1),256>>>(a); }
    // h1 = relu(h0 @ W1 + b1)
    { GArgs a{}; a.A[0][0]=h0p; a.C[0]=h1p;
      a.Bs[0]=W1+(size_t)i*Cn*Cn; a.sB[0]=0; a.bscz[0][0]=1.f; a.kst[0]=Kn/16;
      a.lda=Cn; a.nseg=1; a.sA=(long)Vn*Cn; a.sC=(long)Vn*Cn;
      a.bias=b1+(size_t)i*Cn; a.act=1;
      k_gemm<<<dim3(32,Bn,1),256>>>(a); }
    // x = x + (h1 @ W2 + b2)
    { GArgs a{}; a.A[0][0]=h1p; a.C[0]=xp;
      a.Bs[0]=W2+(size_t)i*Cn*Cn; a.sB[0]=0; a.bscz[0][0]=1.f; a.kst[0]=Kn/16;
      a.lda=Cn; a.nseg=1; a.sA=(long)Vn*Cn; a.sC=(long)Vn*Cn;
      a.bias=b2+(size_t)i*Cn; a.res=xp; a.sRes=(long)Vn*Cn; a.act=0;
      k_gemm<<<dim3(32,Bn,1),256>>>(a); }
  }
  // out = x @ Wl + bl
  { GArgs a{}; a.A[0][0]=xp; a.C[0]=out;
    a.Bs[0]=Wl; a.sB[0]=0; a.bscz[0][0]=1.f; a.kst[0]=Kn/16;
    a.lda=Cn; a.nseg=1; a.sA=(long)Vn*Cn; a.sC=(long)Vn*Cn;
    a.bias=bl; a.act=0;
    k_gemm<<<dim3(32,Bn,1),256>>>(a); }
}

// round 10
// speedup vs baseline: 2.1372x; 1.0354x over previous
#include <cuda_runtime.h>
#include <cuda_fp16.h>
#include <cstdint>

#define Bn 4
#define Vn 4096
#define Kn 128
#define Cn 128
#define NS 32

// ---- scratch (allocation-free rule: __device__ globals) ----
__device__ float g_GXE[Bn*Vn*Kn], g_GYE[Bn*Vn*Kn];
__device__ float g_x[Bn*Vn*Cn], g_xd[Bn*Vn*Cn], g_gx[Bn*Vn*Cn], g_gy[Bn*Vn*Cn];
__device__ float g_Sp[Bn*NS*Kn*Cn], g_D[Bn*Kn*Cn];

// A tiles: [128 m][16 k] halves, row stride 48B -> conflict-free ldmatrix
// B tiles: [16 k][128 n] halves, row stride 272B
#define SA_B 48
#define SB_B 272

// k_mlp dynamic smem map
#define S_AH 0
#define S_AL 6144
#define S_BH 12288
#define S_BL 16640
#define S_BR 20992                 // f32 [128][130] = 66560
#define S_T1H 87552                // A-format full-K tile 1 (gf, then h1)
#define S_T1L (S_T1H+34816)
#define S_T2H 157184               // tile 2 (h0)
#define S_T2L (S_T2H+34816)
#define SMEM_MLP 226816

__device__ __forceinline__ uint32_t s2u(const void* p){
  uint32_t a; asm("{ .reg .u64 t; cvta.to.shared.u64 t, %1; cvt.u32.u64 %0, t; }":"=r"(a):"l"(p));
  return a;
}
__device__ __forceinline__ uint32_t packh(__half a, __half b){
  __half2 t=__halves2half2(a,b); return *(uint32_t*)&t;
}
__device__ __forceinline__ void split2(float x, __half& h, __half& l){
  h=__float2half_rn(x); l=__float2half_rn(x-__half2float(h));
}
__device__ __forceinline__ void ldsm4(uint32_t a, uint32_t* r){
  asm volatile("ldmatrix.sync.aligned.m8n8.x4.shared.b16 {%0,%1,%2,%3},[%4];"
    :"=r"(r[0]),"=r"(r[1]),"=r"(r[2]),"=r"(r[3]):"r"(a));
}
__device__ __forceinline__ void ldsm4t(uint32_t a, uint32_t* r){
  asm volatile("ldmatrix.sync.aligned.m8n8.x4.trans.shared.b16 {%0,%1,%2,%3},[%4];"
    :"=r"(r[0]),"=r"(r[1]),"=r"(r[2]),"=r"(r[3]):"r"(a));
}
__device__ __forceinline__ void mma16(float* d, const uint32_t* a, uint32_t b0, uint32_t b1){
  asm volatile("mma.sync.aligned.m16n8k16.row.col.f32.f16.f16.f32 "
    "{%0,%1,%2,%3},{%4,%5,%6,%7},{%8,%9},{%0,%1,%2,%3};"
    : "+f"(d[0]),"+f"(d[1]),"+f"(d[2]),"+f"(d[3])
    : "r"(a[0]),"r"(a[1]),"r"(a[2]),"r"(a[3]),"r"(b0),"r"(b1));
}
__device__ __forceinline__ void zacc(float (&a)[2][8][4]){
#pragma unroll
  for(int i=0;i<2;i++)
#pragma unroll
  for(int j=0;j<8;j++)
#pragma unroll
  for(int q=0;q<4;q++) a[i][j][q]=0.f;
}

// ---- gmem->regs prefetch ----
__device__ __forceinline__ void ldA(const float* A, int lda, int tid, float4* r){
#pragma unroll
  for(int i=0;i<2;i++){ int idx=tid+i*256;
    r[i]=*(const float4*)(A+(size_t)(idx>>2)*lda+((idx&3)<<2)); }
}
__device__ __forceinline__ void ldB(const float* S, int lds, int tid, float4* r){
#pragma unroll
  for(int i=0;i<2;i++){ int idx=tid+i*256;
    r[i]=*(const float4*)(S+(size_t)(idx&15)*lds+(((idx>>4)&31)<<2)); }
}
// ---- regs->smem staging with fp16 hi/lo split ----
__device__ __forceinline__ void stA(char* H, char* L, const float4* r, int tid){
#pragma unroll
  for(int i=0;i<2;i++){
    int idx=tid+i*256; int m=idx>>2, kq=(idx&3)<<2;
    float4 v=r[i];
    __half h0,h1,h2,h3,l0,l1,l2,l3;
    split2(v.x,h0,l0); split2(v.y,h1,l1); split2(v.z,h2,l2); split2(v.w,h3,l3);
    *(uint2*)(H+m*SA_B+kq*2)=make_uint2(packh(h0,h1),packh(h2,h3));
    *(uint2*)(L+m*SA_B+kq*2)=make_uint2(packh(l0,l1),packh(l2,l3));
  }
}
__device__ __forceinline__ void stB(char* H, char* L, const float4* r, int tid,
                                    const float* si){
#pragma unroll
  for(int i=0;i<2;i++){
    int idx=tid+i*256; int k=idx&15, nq=((idx>>4)&31)<<2;
    float s=si[i];
    float4 v=r[i];
    __half h0,h1,h2,h3,l0,l1,l2,l3;
    split2(v.x*s,h0,l0); split2(v.y*s,h1,l1); split2(v.z*s,h2,l2); split2(v.w*s,h3,l3);
    *(uint2*)(H+k*SB_B+nq*2)=make_uint2(packh(h0,h1),packh(h2,h3));
    *(uint2*)(L+k*SB_B+nq*2)=make_uint2(packh(l0,l1),packh(l2,l3));
  }
}
// transposed A staging (for k_spec: A = E^T): source [16 k][128 m] -> A layout [m][k]
__device__ __forceinline__ void stTA(char* H, char* L, const float4* r, int tid){
#pragma unroll
  for(int i=0;i<2;i++){
    int idx=tid+i*256; int k=idx&15, nq=((idx>>4)&31)<<2;
    float4 v=r[i];
    float e[4]={v.x,v.y,v.z,v.w};
#pragma unroll
    for(int j=0;j<4;j++){
      __half h,l; split2(e[j],h,l);
      *(__half*)(H+(nq+j)*SA_B+k*2)=h;
      *(__half*)(L+(nq+j)*SA_B+k*2)=l;
    }
  }
}

// one 16-deep K step: double-fp16 (3 mma / k16), warp tile 32x64, 8 warps -> 128x128
// sA = A row stride in bytes (48 for staged 16k tiles, 272 for resident full-K tiles)
__device__ __forceinline__ void gstep(uint32_t aH, uint32_t aL, int sA,
                                      uint32_t bH, uint32_t bL,
                                      float (&acc)[2][8][4], int wm,int wn,int lane){
  int lr=lane&15, lc=lane>>4;
  uint32_t ah[2][4], al[2][4];
#pragma unroll
  for(int mt=0;mt<2;mt++){
    uint32_t off=(uint32_t)((wm*32+mt*16+lr)*sA+lc*16);
    ldsm4(aH+off, ah[mt]); ldsm4(aL+off, al[mt]);
  }
#pragma unroll
  for(int bt=0;bt<4;bt++){
    uint32_t bh[4], bl[4];
    uint32_t off=(uint32_t)(lr*SB_B+(wn*64+bt*16+lc*8)*2);
    ldsm4t(bH+off, bh); ldsm4t(bL+off, bl);
#pragma unroll
    for(int j=0;j<2;j++){
      int nt=bt*2+j;
#pragma unroll
      for(int mt=0;mt<2;mt++){
        mma16(acc[mt][nt], ah[mt], bh[2*j], bh[2*j+1]);
        mma16(acc[mt][nt], ah[mt], bl[2*j], bl[2*j+1]);
        mma16(acc[mt][nt], al[mt], bh[2*j], bh[2*j+1]);
      }
    }
  }
}

struct GArgs {
  const float* A[3][3];   // [z][seg]
  float* C[3];            // [z]
  const float* Bs[3]; long sB[3]; int kst[3];  // kst in 16-wide tiles
  float bscz[3][3];       // [z][seg]
  int lda, nseg;
  long sA, sC;
  const float* bias; const float* res; long sRes;
  int act;                // 1 = relu
};

__global__ void __launch_bounds__(256) k_gemm(GArgs ga){
  __shared__ __align__(16) char AhB[128*SA_B], AlB[128*SA_B];
  __shared__ __align__(16) char BhB[16*SB_B],  BlB[16*SB_B];
  int tid=threadIdx.x, lane=tid&31, w=tid>>5, wm=w&3, wn=w>>2;
  uint32_t aH=s2u(AhB), aL=s2u(AlB), bH=s2u(BhB), bL=s2u(BlB);
  float acc[2][8][4]={};
  int mt=blockIdx.x, b=blockIdx.y, z=blockIdx.z;
  int T=0;
#pragma unroll
  for(int s=0;s<3;s++) if(s<ga.nseg) T+=ga.kst[s];
  int seg=0,k0=0;
  const float* As   = ga.A[z][0] + (size_t)b*ga.sA + (size_t)mt*128*ga.lda;
  const float* Bsrc = ga.Bs[0]   + (size_t)b*ga.sB[0];
  float sc = ga.bscz[z][0];
  float4 ra[2], rb[2]; float si[2];
  ldA(As, ga.lda, tid, ra);
  ldB(Bsrc, Cn, tid, rb);
  si[0]=si[1]=sc;
  for(int s=0;s<T;s++){
    stA(AhB, AlB, ra, tid);
    stB(BhB, BlB, rb, tid, si);
    __syncthreads();
    if(s+1<T){
      k0++;
      if(k0==ga.kst[seg]){
        k0=0; seg++;
        As   = ga.A[z][seg] + (size_t)b*ga.sA + (size_t)mt*128*ga.lda;
        Bsrc = ga.Bs[seg]   + (size_t)b*ga.sB[seg];
        sc = ga.bscz[z][seg];
      }
      ldA(As + k0*16, ga.lda, tid, ra);
      ldB(Bsrc + (size_t)k0*16*Cn, Cn, tid, rb);
      si[0]=si[1]=sc;
    }
    gstep(aH,aL,SA_B,bH,bL,acc,wm,wn,lane);
    __syncthreads();
  }
  float* Cg = ga.C[z] + (size_t)b*ga.sC + (size_t)mt*128*Cn;
  const float* Rg = ga.res ? ga.res + (size_t)b*ga.sRes + (size_t)mt*128*Cn : nullptr;
  int er=lane>>2, ec=lane&3;
#pragma unroll
  for(int m2=0;m2<2;m2++)
#pragma unroll
  for(int nt=0;nt<8;nt++){
    int row=wm*32+m2*16+er, col=wn*64+nt*8+2*ec;
    float* av=acc[m2][nt];
#pragma unroll
    for(int rr=0;rr<2;rr++){
      int R=row+rr*8;
      float v0=av[rr*2], v1=av[rr*2+1];
      if(ga.bias){ v0+=ga.bias[col]; v1+=ga.bias[col+1]; }
      if(ga.act==1){ v0=fmaxf(v0,0.f); v1=fmaxf(v1,0.f); }
      if(Rg){ v0+=Rg[(size_t)R*Cn+col]; v1+=Rg[(size_t)R*Cn+col+1]; }
      Cg[(size_t)R*Cn+col]=v0; Cg[(size_t)R*Cn+col+1]=v1;
    }
  }
}

// ---- fused per-block MLP: br/bi -> gfeat -> h0 -> h1 -> h2(+residual) ----
struct MSeg { const float* A; const float* Bw; float sc; int resOff; }; // A==null -> resident

__device__ __forceinline__ void ugemm(char* sm, const MSeg* segs, int nseg,
    float (&acc)[2][8][4], int tid, int wm, int wn, int lane){
  uint32_t sb=s2u(sm);
  for(int s=0;s<nseg;s++){
    const float* A=segs[s].A;
    const float* Bw=segs[s].Bw;
    float si[2]={segs[s].sc,segs[s].sc};
    int ro=segs[s].resOff;
    float4 ra[2], rb[2];
    if(A) ldA(A, Cn, tid, ra);
    ldB(Bw, Cn, tid, rb);
    for(int ks=0;ks<8;ks++){
      if(A) stA(sm+S_AH, sm+S_AL, ra, tid);
      stB(sm+S_BH, sm+S_BL, rb, tid, si);
      __syncthreads();
      if(ks<7){
        if(A) ldA(A+(ks+1)*16, Cn, tid, ra);
        ldB(Bw+(size_t)(ks+1)*16*Cn, Cn, tid, rb);
      }
      if(A) gstep(sb+S_AH, sb+S_AL, SA_B, sb+S_BH, sb+S_BL, acc, wm, wn, lane);
      else  gstep(sb+ro+ks*32, sb+ro+34816+ks*32, 272, sb+S_BH, sb+S_BL, acc, wm, wn, lane);
      __syncthreads();
    }
  }
}

__device__ __forceinline__ void epi_split(char* sm, int Hoff, int Loff,
    float (&acc)[2][8][4], const float* bias, int relu, int wm, int wn, int lane){
  int er=lane>>2, ec=lane&3;
#pragma unroll
  for(int m2=0;m2<2;m2++)
#pragma unroll
  for(int nt=0;nt<8;nt++){
    int row=wm*32+m2*16+er, col=wn*64+nt*8+2*ec;
#pragma unroll
    for(int rr=0;rr<2;rr++){
      int R=row+rr*8;
      float v0=acc[m2][nt][rr*2]+bias[col], v1=acc[m2][nt][rr*2+1]+bias[col+1];
      if(relu){ v0=fmaxf(v0,0.f); v1=fmaxf(v1,0.f); }
      __half h0v,l0v,h1v,l1v; split2(v0,h0v,l0v); split2(v1,h1v,l1v);
      *(uint32_t*)(sm+Hoff+R*272+col*2)=packh(h0v,h1v);
      *(uint32_t*)(sm+Loff+R*272+col*2)=packh(l0v,l1v);
    }
  }
}

__global__ void __launch_bounds__(256) k_mlp(const float* Are,const float* Aim,
    const float* W0,const float* b0,const float* W1,const float* b1,
    const float* W2,const float* b2){
  extern __shared__ char sm[];
  int tid=threadIdx.x, lane=tid&31, w=tid>>5, wm=w&3, wn=w>>2;
  int mt=blockIdx.x, b=blockIdx.y;
  size_t rowoff=(size_t)b*Vn*Cn+(size_t)mt*128*Cn;
  const float* gx=g_gx+rowoff; const float* gy=g_gy+rowoff;
  const float* xd=g_xd+rowoff;
  float* xr=g_x+rowoff;
  float acc[2][8][4];
  int er=lane>>2, ec=lane&3;

  // br = gx@Are - gy@Aim  -> f32 smem
  zacc(acc);
  { MSeg s[2]={{gx,Are,1.f,-1},{gy,Aim,-1.f,-1}}; ugemm(sm,s,2,acc,tid,wm,wn,lane); }
#pragma unroll
  for(int m2=0;m2<2;m2++)
#pragma unroll
  for(int nt=0;nt<8;nt++){
    int row=wm*32+m2*16+er, col=wn*64+nt*8+2*ec;
#pragma unroll
    for(int rr=0;rr<2;rr++){
      int R=row+rr*8;
      *(float2*)(sm+S_BR+((size_t)R*130+col)*4)=
          make_float2(acc[m2][nt][rr*2],acc[m2][nt][rr*2+1]);
    }
  }
  // bi = gy@Are + gx@Aim
  zacc(acc);
  { MSeg s[2]={{gy,Are,1.f,-1},{gx,Aim,1.f,-1}}; ugemm(sm,s,2,acc,tid,wm,wn,lane); }
  // gfeat = tanh(gx*br + gy*bi) -> A-format split at T1
#pragma unroll
  for(int m2=0;m2<2;m2++)
#pragma unroll
  for(int nt=0;nt<8;nt++){
    int row=wm*32+m2*16+er, col=wn*64+nt*8+2*ec;
#pragma unroll
    for(int rr=0;rr<2;rr++){
      int R=row+rr*8;
      float2 brv=*(float2*)(sm+S_BR+((size_t)R*130+col)*4);
      float gx0=gx[(size_t)R*Cn+col], gx1=gx[(size_t)R*Cn+col+1];
      float gy0=gy[(size_t)R*Cn+col], gy1=gy[(size_t)R*Cn+col+1];
      float v0=tanhf(gx0*brv.x+gy0*acc[m2][nt][rr*2]);
      float v1=tanhf(gx1*brv.y+gy1*acc[m2][nt][rr*2+1]);
      __half h0v,l0v,h1v,l1v; split2(v0,h0v,l0v); split2(v1,h1v,l1v);
      *(uint32_t*)(sm+S_T1H+R*272+col*2)=packh(h0v,h1v);
      *(uint32_t*)(sm+S_T1L+R*272+col*2)=packh(l0v,l1v);
    }
  }
  __syncthreads();
  // h0 = relu([x|xd|gf]@W0 + b0) -> T2
  zacc(acc);
  { MSeg s[3]={{xr,W0,1.f,-1},{xd,W0+128*Cn,1.f,-1},{nullptr,W0+256*Cn,1.f,S_T1H}};
    ugemm(sm,s,3,acc,tid,wm,wn,lane); }
  epi_split(sm,S_T2H,S_T2L,acc,b0,1,wm,wn,lane);
  __syncthreads();
  // h1 = relu(h0@W1 + b1) -> T1
  zacc(acc);
  { MSeg s[1]={{nullptr,W1,1.f,S_T2H}}; ugemm(sm,s,1,acc,tid,wm,wn,lane); }
  epi_split(sm,S_T1H,S_T1L,acc,b1,1,wm,wn,lane);
  __syncthreads();
  // x += h1@W2 + b2
  zacc(acc);
  { MSeg s[1]={{nullptr,W2,1.f,S_T1H}}; ugemm(sm,s,1,acc,tid,wm,wn,lane); }
#pragma unroll
  for(int m2=0;m2<2;m2++)
#pragma unroll
  for(int nt=0;nt<8;nt++){
    int row=wm*32+m2*16+er, col=wn*64+nt*8+2*ec;
#pragma unroll
    for(int rr=0;rr<2;rr++){
      int R=row+rr*8;
      float v0=acc[m2][nt][rr*2]+b2[col]+xr[(size_t)R*Cn+col];
      float v1=acc[m2][nt][rr*2+1]+b2[col+1]+xr[(size_t)R*Cn+col+1];
      xr[(size_t)R*Cn+col]=v0; xr[(size_t)R*Cn+col+1]=v1;
    }
  }
}

// x_spec split-K partials: Sp[b,sp] = E[v0:v0+V/NS]^T @ (x*mass)[v0:v0+V/NS]
__global__ void __launch_bounds__(256) k_spec(const float* E, const float* mass){
  __shared__ __align__(16) char AhB[128*SA_B], AlB[128*SA_B];
  __shared__ __align__(16) char BhB[16*SB_B],  BlB[16*SB_B];
  int tid=threadIdx.x, lane=tid&31, w=tid>>5, wm=w&3, wn=w>>2;
  uint32_t aH=s2u(AhB), aL=s2u(AlB), bH=s2u(BhB), bL=s2u(BlB);
  float acc[2][8][4]={};
  int b=blockIdx.x, sp=blockIdx.y;
  const float* Eb=E+(size_t)b*Vn*Kn;
  const float* Xb=g_x+(size_t)b*Vn*Cn;
  const float* Mb=mass+(size_t)b*Vn;
  int v0=sp*(Vn/NS);
  const int T=(Vn/NS)/16;
  float4 ra[2], rb[2]; float ms[2];
  ldB(Eb+(size_t)v0*Kn, Kn, tid, ra);
  ldB(Xb+(size_t)v0*Cn, Cn, tid, rb);
#pragma unroll
  for(int i=0;i<2;i++){ int idx=tid+i*256; ms[i]=Mb[v0+(idx&15)]; }
  for(int s=0;s<T;s++){
    stTA(AhB, AlB, ra, tid);
    stB(BhB, BlB, rb, tid, ms);
    __syncthreads();
    if(s+1<T){
      int v=v0+(s+1)*16;
      ldB(Eb+(size_t)v*Kn, Kn, tid, ra);
      ldB(Xb+(size_t)v*Cn, Cn, tid, rb);
#pragma unroll
      for(int i=0;i<2;i++){ int idx=tid+i*256; ms[i]=Mb[v+(idx&15)]; }
    }
    gstep(aH,aL,SA_B,bH,bL,acc,wm,wn,lane);
    __syncthreads();
  }
  float* Cg=g_Sp+(size_t)(b*NS+sp)*Kn*Cn;
  int er=lane>>2, ec=lane&3;
#pragma unroll
  for(int m2=0;m2<2;m2++)
#pragma unroll
  for(int nt=0;nt<8;nt++){
    int row=wm*32+m2*16+er, col=wn*64+nt*8+2*ec;
    float* av=acc[m2][nt];
    *(float2*)&Cg[(size_t)row*Cn+col]     = make_float2(av[0],av[1]);
    *(float2*)&Cg[(size_t)(row+8)*Cn+col] = make_float2(av[2],av[3]);
  }
}

// reduce NS split partials + apply diffusion coefficients
__global__ void k_coef(const float* evals, const float* t, int blk){
  int b=blockIdx.x;
  int base=blockIdx.y*1024;
  const float* tb=t+blk*Cn;
  for(int i=threadIdx.x; i<1024; i+=blockDim.x){
    int idx=base+i;
    int k=idx>>7, c=idx&127;
    float s=0.f;
#pragma unroll
    for(int sp=0;sp<NS;sp++) s+=g_Sp[(size_t)(b*NS+sp)*Kn*Cn+idx];
    g_D[(size_t)b*Kn*Cn+idx]=expf(-evals[b*Kn+k]*fmaxf(tb[c],1e-8f))*s;
  }
}

// x = x_in @ Wf + bf  (K=16, tiny)
__global__ void k_x0(const float* xi, const float* Wf, const float* bf){
  __shared__ float w[16*128];
  __shared__ float xs[16][17];
  int tid=threadIdx.x;
  for(int i=tid;i<2048;i+=128) w[i]=Wf[i];
  int r0=blockIdx.x*16;
  for(int i=tid;i<256;i+=128) xs[i>>4][i&15]=xi[(size_t)r0*16+i];
  __syncthreads();
  float bv=bf[tid];
#pragma unroll
  for(int rr=0;rr<16;rr++){
    float s=bv;
#pragma unroll
    for(int k=0;k<16;k++) s+=xs[rr][k]*w[k*128+tid];
    g_x[(size_t)(r0+rr)*Cn+tid]=s;
  }
}

extern "C" void kernel_launch(void* const* d_in, const int* in_sizes, int n_in,
                              void* d_out, int out_size){
  const float *x_in=(const float*)d_in[0], *mass=(const float*)d_in[1],
    *evals=(const float*)d_in[2], *evecs=(const float*)d_in[3],
    *gradX=(const float*)d_in[4], *gradY=(const float*)d_in[5],
    *Wf=(const float*)d_in[6], *bf=(const float*)d_in[7],
    *Wl=(const float*)d_in[8], *bl=(const float*)d_in[9],
    *t=(const float*)d_in[10], *Are=(const float*)d_in[11], *Aim=(const float*)d_in[12],
    *W0=(const float*)d_in[13], *b0=(const float*)d_in[14],
    *W1=(const float*)d_in[15], *b1=(const float*)d_in[16],
    *W2=(const float*)d_in[17], *b2=(const float*)d_in[18];
  float* out=(float*)d_out;

  cudaFuncSetAttribute(k_mlp, cudaFuncAttributeMaxDynamicSharedMemorySize, SMEM_MLP);

  float *GXEp,*GYEp,*xp,*xdp,*gxp,*gyp,*Dp;
  cudaGetSymbolAddress((void**)&GXEp,g_GXE); cudaGetSymbolAddress((void**)&GYEp,g_GYE);
  cudaGetSymbolAddress((void**)&xp,g_x);     cudaGetSymbolAddress((void**)&xdp,g_xd);
  cudaGetSymbolAddress((void**)&gxp,g_gx);   cudaGetSymbolAddress((void**)&gyp,g_gy);
  cudaGetSymbolAddress((void**)&Dp,g_D);

  // precompute GXE = gradX@evecs, GYE = gradY@evecs (block-invariant)
  { GArgs a{}; a.A[0][0]=gradX; a.A[1][0]=gradY; a.C[0]=GXEp; a.C[1]=GYEp;
    a.Bs[0]=evecs; a.sB[0]=(long)Vn*Kn; a.bscz[0][0]=1.f; a.bscz[1][0]=1.f;
    a.kst[0]=Vn/16; a.lda=Vn; a.nseg=1; a.sA=(long)Vn*Vn; a.sC=(long)Vn*Kn; a.act=0;
    k_gemm<<<dim3(32,Bn,2),256>>>(a); }

  k_x0<<<Bn*Vn/16,128>>>(x_in,Wf,bf);

  for(int i=0;i<4;i++){
    k_spec<<<dim3(Bn,NS),256>>>(evecs,mass);
    k_coef<<<dim3(Bn,16),256>>>(evals,t,i);
    // x_diff = E@D, gx = GXE@D, gy = GYE@D
    { GArgs a{}; a.A[0][0]=evecs; a.A[1][0]=GXEp; a.A[2][0]=GYEp;
      a.C[0]=xdp; a.C[1]=gxp; a.C[2]=gyp;
      a.Bs[0]=Dp; a.sB[0]=(long)Kn*Cn;
      a.bscz[0][0]=1.f; a.bscz[1][0]=1.f; a.bscz[2][0]=1.f;
      a.kst[0]=Kn/16; a.lda=Kn; a.nseg=1; a.sA=(long)Vn*Kn; a.sC=(long)Vn*Cn; a.act=0;
      k_gemm<<<dim3(32,Bn,3),256>>>(a); }
    // fused: br/bi -> gfeat -> h0 -> h1 -> x += h2
    k_mlp<<<dim3(32,Bn),256,SMEM_MLP>>>(
        Are+(size_t)i*Cn*Cn, Aim+(size_t)i*Cn*Cn,
        W0+(size_t)i*384*Cn, b0+(size_t)i*Cn,
        W1+(size_t)i*Cn*Cn,  b1+(size_t)i*Cn,
        W2+(size_t)i*Cn*Cn,  b2+(size_t)i*Cn);
  }
  // out = x @ Wl + bl
  { GArgs a{}; a.A[0][0]=xp; a.C[0]=out;
    a.Bs[0]=Wl; a.sB[0]=0; a.bscz[0][0]=1.f; a.kst[0]=Kn/16;
    a.lda=Cn; a.nseg=1; a.sA=(long)Vn*Cn; a.sC=(long)Vn*Cn;
    a.bias=bl; a.act=0;
    k_gemm<<<dim3(32,Bn,1),256>>>(a); }
}

// round 11
// speedup vs baseline: 2.1484x; 1.0053x over previous
#include <cuda_runtime.h>
#include <cuda_fp16.h>
#include <cstdint>

#define Bn 4
#define Vn 4096
#define Kn 128
#define Cn 128
#define NS 32

// ---- scratch (allocation-free rule: __device__ globals) ----
__device__ float g_GXE[Bn*Vn*Kn], g_GYE[Bn*Vn*Kn];
__device__ float g_x[Bn*Vn*Cn], g_xd[Bn*Vn*Cn], g_gx[Bn*Vn*Cn], g_gy[Bn*Vn*Cn];
__device__ float g_Sp[Bn*NS*Kn*Cn], g_D[Bn*Kn*Cn];

// A tiles: [128 m][16 k] halves, row stride 48B -> conflict-free ldmatrix
// B tiles: [16 k][128 n] halves, row stride 272B
#define SA_B 48
#define SB_B 272

// k_mlp dynamic smem map
#define S_AH 0
#define S_AL 6144
#define S_BH 12288
#define S_BL 16640
#define S_BR 20992                 // f32 [128][130] = 66560
#define S_T1H 87552                // A-format full-K tile 1 (gf, then h1)
#define S_T1L (S_T1H+34816)
#define S_T2H 157184               // tile 2 (h0)
#define S_T2L (S_T2H+34816)
#define SMEM_MLP 226816

__device__ __forceinline__ uint32_t s2u(const void* p){
  uint32_t a; asm("{ .reg .u64 t; cvta.to.shared.u64 t, %1; cvt.u32.u64 %0, t; }":"=r"(a):"l"(p));
  return a;
}
__device__ __forceinline__ uint32_t packh(__half a, __half b){
  __half2 t=__halves2half2(a,b); return *(uint32_t*)&t;
}
__device__ __forceinline__ void split2(float x, __half& h, __half& l){
  h=__float2half_rn(x); l=__float2half_rn(x-__half2float(h));
}
__device__ __forceinline__ void ldsm4(uint32_t a, uint32_t* r){
  asm volatile("ldmatrix.sync.aligned.m8n8.x4.shared.b16 {%0,%1,%2,%3},[%4];"
    :"=r"(r[0]),"=r"(r[1]),"=r"(r[2]),"=r"(r[3]):"r"(a));
}
__device__ __forceinline__ void ldsm4t(uint32_t a, uint32_t* r){
  asm volatile("ldmatrix.sync.aligned.m8n8.x4.trans.shared.b16 {%0,%1,%2,%3},[%4];"
    :"=r"(r[0]),"=r"(r[1]),"=r"(r[2]),"=r"(r[3]):"r"(a));
}
__device__ __forceinline__ void mma16(float* d, const uint32_t* a, uint32_t b0, uint32_t b1){
  asm volatile("mma.sync.aligned.m16n8k16.row.col.f32.f16.f16.f32 "
    "{%0,%1,%2,%3},{%4,%5,%6,%7},{%8,%9},{%0,%1,%2,%3};"
    : "+f"(d[0]),"+f"(d[1]),"+f"(d[2]),"+f"(d[3])
    : "r"(a[0]),"r"(a[1]),"r"(a[2]),"r"(a[3]),"r"(b0),"r"(b1));
}
__device__ __forceinline__ void zacc(float (&a)[2][8][4]){
#pragma unroll
  for(int i=0;i<2;i++)
#pragma unroll
  for(int j=0;j<8;j++)
#pragma unroll
  for(int q=0;q<4;q++) a[i][j][q]=0.f;
}

// ---- gmem->regs prefetch ----
__device__ __forceinline__ void ldA(const float* A, int lda, int tid, float4* r){
#pragma unroll
  for(int i=0;i<2;i++){ int idx=tid+i*256;
    r[i]=*(const float4*)(A+(size_t)(idx>>2)*lda+((idx&3)<<2)); }
}
__device__ __forceinline__ void ldB(const float* S, int lds, int tid, float4* r){
#pragma unroll
  for(int i=0;i<2;i++){ int idx=tid+i*256;
    r[i]=*(const float4*)(S+(size_t)(idx&15)*lds+(((idx>>4)&31)<<2)); }
}
// ---- regs->smem staging with fp16 hi/lo split ----
__device__ __forceinline__ void stA(char* H, char* L, const float4* r, int tid){
#pragma unroll
  for(int i=0;i<2;i++){
    int idx=tid+i*256; int m=idx>>2, kq=(idx&3)<<2;
    float4 v=r[i];
    __half h0,h1,h2,h3,l0,l1,l2,l3;
    split2(v.x,h0,l0); split2(v.y,h1,l1); split2(v.z,h2,l2); split2(v.w,h3,l3);
    *(uint2*)(H+m*SA_B+kq*2)=make_uint2(packh(h0,h1),packh(h2,h3));
    *(uint2*)(L+m*SA_B+kq*2)=make_uint2(packh(l0,l1),packh(l2,l3));
  }
}
__device__ __forceinline__ void stB(char* H, char* L, const float4* r, int tid,
                                    const float* si){
#pragma unroll
  for(int i=0;i<2;i++){
    int idx=tid+i*256; int k=idx&15, nq=((idx>>4)&31)<<2;
    float s=si[i];
    float4 v=r[i];
    __half h0,h1,h2,h3,l0,l1,l2,l3;
    split2(v.x*s,h0,l0); split2(v.y*s,h1,l1); split2(v.z*s,h2,l2); split2(v.w*s,h3,l3);
    *(uint2*)(H+k*SB_B+nq*2)=make_uint2(packh(h0,h1),packh(h2,h3));
    *(uint2*)(L+k*SB_B+nq*2)=make_uint2(packh(l0,l1),packh(l2,l3));
  }
}
// transposed A staging (for k_spec: A = E^T): source [16 k][128 m] -> A layout [m][k]
__device__ __forceinline__ void stTA(char* H, char* L, const float4* r, int tid){
#pragma unroll
  for(int i=0;i<2;i++){
    int idx=tid+i*256; int k=idx&15, nq=((idx>>4)&31)<<2;
    float4 v=r[i];
    float e[4]={v.x,v.y,v.z,v.w};
#pragma unroll
    for(int j=0;j<4;j++){
      __half h,l; split2(e[j],h,l);
      *(__half*)(H+(nq+j)*SA_B+k*2)=h;
      *(__half*)(L+(nq+j)*SA_B+k*2)=l;
    }
  }
}

// one 16-deep K step: double-fp16, warp tile 32x64, 8 warps -> 128x128
// three=1: ah*bh + ah*bl + al*bh (eps~2^-22); three=0: ah*bh + al*bh (A exact, B hi)
__device__ __forceinline__ void gstep(uint32_t aH, uint32_t aL, int sA,
                                      uint32_t bH, uint32_t bL,
                                      float (&acc)[2][8][4], int wm,int wn,int lane,
                                      int three){
  int lr=lane&15, lc=lane>>4;
  uint32_t ah[2][4], al[2][4];
#pragma unroll
  for(int mt=0;mt<2;mt++){
    uint32_t off=(uint32_t)((wm*32+mt*16+lr)*sA+lc*16);
    ldsm4(aH+off, ah[mt]); ldsm4(aL+off, al[mt]);
  }
#pragma unroll
  for(int bt=0;bt<4;bt++){
    uint32_t bh[4], bl[4];
    uint32_t off=(uint32_t)(lr*SB_B+(wn*64+bt*16+lc*8)*2);
    ldsm4t(bH+off, bh);
    if(three) ldsm4t(bL+off, bl);
#pragma unroll
    for(int j=0;j<2;j++){
      int nt=bt*2+j;
#pragma unroll
      for(int mt=0;mt<2;mt++){
        mma16(acc[mt][nt], ah[mt], bh[2*j], bh[2*j+1]);
        if(three) mma16(acc[mt][nt], ah[mt], bl[2*j], bl[2*j+1]);
        mma16(acc[mt][nt], al[mt], bh[2*j], bh[2*j+1]);
      }
    }
  }
}

struct GArgs {
  const float* A[3][3];   // [z][seg]
  float* C[3];            // [z]
  const float* Bs[3]; long sB[3]; int kst[3];  // kst in 16-wide tiles
  float bscz[3][3];       // [z][seg]
  int lda, nseg;
  long sA, sC;
  const float* bias; const float* res; long sRes;
  int act;                // 1 = relu
  int terms;              // 3 or 2
};

__global__ void __launch_bounds__(256) k_gemm(GArgs ga){
  __shared__ __align__(16) char AhB[128*SA_B], AlB[128*SA_B];
  __shared__ __align__(16) char BhB[16*SB_B],  BlB[16*SB_B];
  int tid=threadIdx.x, lane=tid&31, w=tid>>5, wm=w&3, wn=w>>2;
  uint32_t aH=s2u(AhB), aL=s2u(AlB), bH=s2u(BhB), bL=s2u(BlB);
  float acc[2][8][4]={};
  int mt=blockIdx.x, b=blockIdx.y, z=blockIdx.z;
  int three=(ga.terms==3);
  int T=0;
#pragma unroll
  for(int s=0;s<3;s++) if(s<ga.nseg) T+=ga.kst[s];
  int seg=0,k0=0;
  const float* As   = ga.A[z][0] + (size_t)b*ga.sA + (size_t)mt*128*ga.lda;
  const float* Bsrc = ga.Bs[0]   + (size_t)b*ga.sB[0];
  float sc = ga.bscz[z][0];
  float4 ra[2], rb[2]; float si[2];
  ldA(As, ga.lda, tid, ra);
  ldB(Bsrc, Cn, tid, rb);
  si[0]=si[1]=sc;
  for(int s=0;s<T;s++){
    stA(AhB, AlB, ra, tid);
    stB(BhB, BlB, rb, tid, si);
    __syncthreads();
    if(s+1<T){
      k0++;
      if(k0==ga.kst[seg]){
        k0=0; seg++;
        As   = ga.A[z][seg] + (size_t)b*ga.sA + (size_t)mt*128*ga.lda;
        Bsrc = ga.Bs[seg]   + (size_t)b*ga.sB[seg];
        sc = ga.bscz[z][seg];
      }
      ldA(As + k0*16, ga.lda, tid, ra);
      ldB(Bsrc + (size_t)k0*16*Cn, Cn, tid, rb);
      si[0]=si[1]=sc;
    }
    gstep(aH,aL,SA_B,bH,bL,acc,wm,wn,lane,three);
    __syncthreads();
  }
  float* Cg = ga.C[z] + (size_t)b*ga.sC + (size_t)mt*128*Cn;
  const float* Rg = ga.res ? ga.res + (size_t)b*ga.sRes + (size_t)mt*128*Cn : nullptr;
  int er=lane>>2, ec=lane&3;
#pragma unroll
  for(int m2=0;m2<2;m2++)
#pragma unroll
  for(int nt=0;nt<8;nt++){
    int row=wm*32+m2*16+er, col=wn*64+nt*8+2*ec;
    float* av=acc[m2][nt];
#pragma unroll
    for(int rr=0;rr<2;rr++){
      int R=row+rr*8;
      float v0=av[rr*2], v1=av[rr*2+1];
      if(ga.bias){ v0+=ga.bias[col]; v1+=ga.bias[col+1]; }
      if(ga.act==1){ v0=fmaxf(v0,0.f); v1=fmaxf(v1,0.f); }
      if(Rg){ v0+=Rg[(size_t)R*Cn+col]; v1+=Rg[(size_t)R*Cn+col+1]; }
      Cg[(size_t)R*Cn+col]=v0; Cg[(size_t)R*Cn+col+1]=v1;
    }
  }
}

// ---- fused per-block MLP: br/bi -> gfeat -> h0 -> h1 -> h2(+residual) ----
struct MSeg { const float* A; const float* Bw; float sc; int resOff; }; // A==null -> resident

__device__ __forceinline__ void ugemm(char* sm, const MSeg* segs, int nseg,
    float (&acc)[2][8][4], int tid, int wm, int wn, int lane){
  uint32_t sb=s2u(sm);
  for(int s=0;s<nseg;s++){
    const float* A=segs[s].A;
    const float* Bw=segs[s].Bw;
    float si[2]={segs[s].sc,segs[s].sc};
    int ro=segs[s].resOff;
    float4 ra[2], rb[2];
    if(A) ldA(A, Cn, tid, ra);
    ldB(Bw, Cn, tid, rb);
    for(int ks=0;ks<8;ks++){
      if(A) stA(sm+S_AH, sm+S_AL, ra, tid);
      stB(sm+S_BH, sm+S_BL, rb, tid, si);
      __syncthreads();
      if(ks<7){
        if(A) ldA(A+(ks+1)*16, Cn, tid, ra);
        ldB(Bw+(size_t)(ks+1)*16*Cn, Cn, tid, rb);
      }
      if(A) gstep(sb+S_AH, sb+S_AL, SA_B, sb+S_BH, sb+S_BL, acc, wm, wn, lane, 1);
      else  gstep(sb+ro+ks*32, sb+ro+34816+ks*32, 272, sb+S_BH, sb+S_BL, acc, wm, wn, lane, 1);
      __syncthreads();
    }
  }
}

__device__ __forceinline__ void epi_split(char* sm, int Hoff, int Loff,
    float (&acc)[2][8][4], const float* bias, int relu, int wm, int wn, int lane){
  int er=lane>>2, ec=lane&3;
#pragma unroll
  for(int m2=0;m2<2;m2++)
#pragma unroll
  for(int nt=0;nt<8;nt++){
    int row=wm*32+m2*16+er, col=wn*64+nt*8+2*ec;
#pragma unroll
    for(int rr=0;rr<2;rr++){
      int R=row+rr*8;
      float v0=acc[m2][nt][rr*2]+bias[col], v1=acc[m2][nt][rr*2+1]+bias[col+1];
      if(relu){ v0=fmaxf(v0,0.f); v1=fmaxf(v1,0.f); }
      __half h0v,l0v,h1v,l1v; split2(v0,h0v,l0v); split2(v1,h1v,l1v);
      *(uint32_t*)(sm+Hoff+R*272+col*2)=packh(h0v,h1v);
      *(uint32_t*)(sm+Loff+R*272+col*2)=packh(l0v,l1v);
    }
  }
}

__global__ void __launch_bounds__(256) k_mlp(const float* Are,const float* Aim,
    const float* W0,const float* b0,const float* W1,const float* b1,
    const float* W2,const float* b2){
  extern __shared__ char sm[];
  int tid=threadIdx.x, lane=tid&31, w=tid>>5, wm=w&3, wn=w>>2;
  int mt=blockIdx.x, b=blockIdx.y;
  size_t rowoff=(size_t)b*Vn*Cn+(size_t)mt*128*Cn;
  const float* gx=g_gx+rowoff; const float* gy=g_gy+rowoff;
  const float* xd=g_xd+rowoff;
  float* xr=g_x+rowoff;
  float acc[2][8][4];
  int er=lane>>2, ec=lane&3;

  // br = gx@Are - gy@Aim  -> f32 smem
  zacc(acc);
  { MSeg s[2]={{gx,Are,1.f,-1},{gy,Aim,-1.f,-1}}; ugemm(sm,s,2,acc,tid,wm,wn,lane); }
#pragma unroll
  for(int m2=0;m2<2;m2++)
#pragma unroll
  for(int nt=0;nt<8;nt++){
    int row=wm*32+m2*16+er, col=wn*64+nt*8+2*ec;
#pragma unroll
    for(int rr=0;rr<2;rr++){
      int R=row+rr*8;
      *(float2*)(sm+S_BR+((size_t)R*130+col)*4)=
          make_float2(acc[m2][nt][rr*2],acc[m2][nt][rr*2+1]);
    }
  }
  // bi = gy@Are + gx@Aim
  zacc(acc);
  { MSeg s[2]={{gy,Are,1.f,-1},{gx,Aim,1.f,-1}}; ugemm(sm,s,2,acc,tid,wm,wn,lane); }
  // gfeat = tanh(gx*br + gy*bi) -> A-format split at T1
#pragma unroll
  for(int m2=0;m2<2;m2++)
#pragma unroll
  for(int nt=0;nt<8;nt++){
    int row=wm*32+m2*16+er, col=wn*64+nt*8+2*ec;
#pragma unroll
    for(int rr=0;rr<2;rr++){
      int R=row+rr*8;
      float2 brv=*(float2*)(sm+S_BR+((size_t)R*130+col)*4);
      float gx0=gx[(size_t)R*Cn+col], gx1=gx[(size_t)R*Cn+col+1];
      float gy0=gy[(size_t)R*Cn+col], gy1=gy[(size_t)R*Cn+col+1];
      float v0=tanhf(gx0*brv.x+gy0*acc[m2][nt][rr*2]);
      float v1=tanhf(gx1*brv.y+gy1*acc[m2][nt][rr*2+1]);
      __half h0v,l0v,h1v,l1v; split2(v0,h0v,l0v); split2(v1,h1v,l1v);
      *(uint32_t*)(sm+S_T1H+R*272+col*2)=packh(h0v,h1v);
      *(uint32_t*)(sm+S_T1L+R*272+col*2)=packh(l0v,l1v);
    }
  }
  __syncthreads();
  // h0 = relu([x|xd|gf]@W0 + b0) -> T2
  zacc(acc);
  { MSeg s[3]={{xr,W0,1.f,-1},{xd,W0+128*Cn,1.f,-1},{nullptr,W0+256*Cn,1.f,S_T1H}};
    ugemm(sm,s,3,acc,tid,wm,wn,lane); }
  epi_split(sm,S_T2H,S_T2L,acc,b0,1,wm,wn,lane);
  __syncthreads();
  // h1 = relu(h0@W1 + b1) -> T1
  zacc(acc);
  { MSeg s[1]={{nullptr,W1,1.f,S_T2H}}; ugemm(sm,s,1,acc,tid,wm,wn,lane); }
  epi_split(sm,S_T1H,S_T1L,acc,b1,1,wm,wn,lane);
  __syncthreads();
  // x += h1@W2 + b2
  zacc(acc);
  { MSeg s[1]={{nullptr,W2,1.f,S_T1H}}; ugemm(sm,s,1,acc,tid,wm,wn,lane); }
#pragma unroll
  for(int m2=0;m2<2;m2++)
#pragma unroll
  for(int nt=0;nt<8;nt++){
    int row=wm*32+m2*16+er, col=wn*64+nt*8+2*ec;
#pragma unroll
    for(int rr=0;rr<2;rr++){
      int R=row+rr*8;
      float v0=acc[m2][nt][rr*2]+b2[col]+xr[(size_t)R*Cn+col];
      float v1=acc[m2][nt][rr*2+1]+b2[col+1]+xr[(size_t)R*Cn+col+1];
      xr[(size_t)R*Cn+col]=v0; xr[(size_t)R*Cn+col+1]=v1;
    }
  }
}

// x_spec split-K partials: Sp[b,sp] = E[v0:v0+V/NS]^T @ (x*mass)[v0:v0+V/NS]
__global__ void __launch_bounds__(256) k_spec(const float* E, const float* mass){
  __shared__ __align__(16) char AhB[128*SA_B], AlB[128*SA_B];
  __shared__ __align__(16) char BhB[16*SB_B],  BlB[16*SB_B];
  int tid=threadIdx.x, lane=tid&31, w=tid>>5, wm=w&3, wn=w>>2;
  uint32_t aH=s2u(AhB), aL=s2u(AlB), bH=s2u(BhB), bL=s2u(BlB);
  float acc[2][8][4]={};
  int b=blockIdx.x, sp=blockIdx.y;
  const float* Eb=E+(size_t)b*Vn*Kn;
  const float* Xb=g_x+(size_t)b*Vn*Cn;
  const float* Mb=mass+(size_t)b*Vn;
  int v0=sp*(Vn/NS);
  const int T=(Vn/NS)/16;
  float4 ra[2], rb[2]; float ms[2];
  ldB(Eb+(size_t)v0*Kn, Kn, tid, ra);
  ldB(Xb+(size_t)v0*Cn, Cn, tid, rb);
#pragma unroll
  for(int i=0;i<2;i++){ int idx=tid+i*256; ms[i]=Mb[v0+(idx&15)]; }
  for(int s=0;s<T;s++){
    stTA(AhB, AlB, ra, tid);
    stB(BhB, BlB, rb, tid, ms);
    __syncthreads();
    if(s+1<T){
      int v=v0+(s+1)*16;
      ldB(Eb+(size_t)v*Kn, Kn, tid, ra);
      ldB(Xb+(size_t)v*Cn, Cn, tid, rb);
#pragma unroll
      for(int i=0;i<2;i++){ int idx=tid+i*256; ms[i]=Mb[v+(idx&15)]; }
    }
    gstep(aH,aL,SA_B,bH,bL,acc,wm,wn,lane,1);
    __syncthreads();
  }
  float* Cg=g_Sp+(size_t)(b*NS+sp)*Kn*Cn;
  int er=lane>>2, ec=lane&3;
#pragma unroll
  for(int m2=0;m2<2;m2++)
#pragma unroll
  for(int nt=0;nt<8;nt++){
    int row=wm*32+m2*16+er, col=wn*64+nt*8+2*ec;
    float* av=acc[m2][nt];
    *(float2*)&Cg[(size_t)row*Cn+col]     = make_float2(av[0],av[1]);
    *(float2*)&Cg[(size_t)(row+8)*Cn+col] = make_float2(av[2],av[3]);
  }
}

// reduce NS split partials + apply diffusion coefficients
__global__ void k_coef(const float* evals, const float* t, int blk){
  int b=blockIdx.x;
  int base=blockIdx.y*1024;
  const float* tb=t+blk*Cn;
  for(int i=threadIdx.x; i<1024; i+=blockDim.x){
    int idx=base+i;
    int k=idx>>7, c=idx&127;
    float s=0.f;
#pragma unroll
    for(int sp=0;sp<NS;sp++) s+=g_Sp[(size_t)(b*NS+sp)*Kn*Cn+idx];
    g_D[(size_t)b*Kn*Cn+idx]=expf(-evals[b*Kn+k]*fmaxf(tb[c],1e-8f))*s;
  }
}

// x = x_in @ Wf + bf  (K=16, tiny)
__global__ void k_x0(const float* xi, const float* Wf, const float* bf){
  __shared__ float w[16*128];
  __shared__ float xs[16][17];
  int tid=threadIdx.x;
  for(int i=tid;i<2048;i+=128) w[i]=Wf[i];
  int r0=blockIdx.x*16;
  for(int i=tid;i<256;i+=128) xs[i>>4][i&15]=xi[(size_t)r0*16+i];
  __syncthreads();
  float bv=bf[tid];
#pragma unroll
  for(int rr=0;rr<16;rr++){
    float s=bv;
#pragma unroll
    for(int k=0;k<16;k++) s+=xs[rr][k]*w[k*128+tid];
    g_x[(size_t)(r0+rr)*Cn+tid]=s;
  }
}

extern "C" void kernel_launch(void* const* d_in, const int* in_sizes, int n_in,
                              void* d_out, int out_size){
  const float *x_in=(const float*)d_in[0], *mass=(const float*)d_in[1],
    *evals=(const float*)d_in[2], *evecs=(const float*)d_in[3],
    *gradX=(const float*)d_in[4], *gradY=(const float*)d_in[5],
    *Wf=(const float*)d_in[6], *bf=(const float*)d_in[7],
    *Wl=(const float*)d_in[8], *bl=(const float*)d_in[9],
    *t=(const float*)d_in[10], *Are=(const float*)d_in[11], *Aim=(const float*)d_in[12],
    *W0=(const float*)d_in[13], *b0=(const float*)d_in[14],
    *W1=(const float*)d_in[15], *b1=(const float*)d_in[16],
    *W2=(const float*)d_in[17], *b2=(const float*)d_in[18];
  float* out=(float*)d_out;

  cudaFuncSetAttribute(k_mlp, cudaFuncAttributeMaxDynamicSharedMemorySize, SMEM_MLP);

  float *GXEp,*GYEp,*xp,*xdp,*gxp,*gyp,*Dp;
  cudaGetSymbolAddress((void**)&GXEp,g_GXE); cudaGetSymbolAddress((void**)&GYEp,g_GYE);
  cudaGetSymbolAddress((void**)&xp,g_x);     cudaGetSymbolAddress((void**)&xdp,g_xd);
  cudaGetSymbolAddress((void**)&gxp,g_gx);   cudaGetSymbolAddress((void**)&gyp,g_gy);
  cudaGetSymbolAddress((void**)&Dp,g_D);

  // precompute GXE = gradX@evecs, GYE = gradY@evecs (block-invariant)
  // 2-term split: A (gradX/gradY) exact hi+lo, B (evecs) hi only -> rel err ~1e-4
  { GArgs a{}; a.A[0][0]=gradX; a.A[1][0]=gradY; a.C[0]=GXEp; a.C[1]=GYEp;
    a.Bs[0]=evecs; a.sB[0]=(long)Vn*Kn; a.bscz[0][0]=1.f; a.bscz[1][0]=1.f;
    a.kst[0]=Vn/16; a.lda=Vn; a.nseg=1; a.sA=(long)Vn*Vn; a.sC=(long)Vn*Kn; a.act=0;
    a.terms=2;
    k_gemm<<<dim3(32,Bn,2),256>>>(a); }

  k_x0<<<Bn*Vn/16,128>>>(x_in,Wf,bf);

  for(int i=0;i<4;i++){
    k_spec<<<dim3(Bn,NS),256>>>(evecs,mass);
    k_coef<<<dim3(Bn,16),256>>>(evals,t,i);
    // x_diff = E@D, gx = GXE@D, gy = GYE@D
    { GArgs a{}; a.A[0][0]=evecs; a.A[1][0]=GXEp; a.A[2][0]=GYEp;
      a.C[0]=xdp; a.C[1]=gxp; a.C[2]=gyp;
      a.Bs[0]=Dp; a.sB[0]=(long)Kn*Cn;
      a.bscz[0][0]=1.f; a.bscz[1][0]=1.f; a.bscz[2][0]=1.f;
      a.kst[0]=Kn/16; a.lda=Kn; a.nseg=1; a.sA=(long)Vn*Kn; a.sC=(long)Vn*Cn; a.act=0;
      a.terms=3;
      k_gemm<<<dim3(32,Bn,3),256>>>(a); }
    // fused: br/bi -> gfeat -> h0 -> h1 -> x += h2
    k_mlp<<<dim3(32,Bn),256,SMEM_MLP>>>(
        Are+(size_t)i*Cn*Cn, Aim+(size_t)i*Cn*Cn,
        W0+(size_t)i*384*Cn, b0+(size_t)i*Cn,
        W1+(size_t)i*Cn*Cn,  b1+(size_t)i*Cn,
        W2+(size_t)i*Cn*Cn,  b2+(size_t)i*Cn);
  }
  // out = x @ Wl + bl
  { GArgs a{}; a.A[0][0]=xp; a.C[0]=out;
    a.Bs[0]=Wl; a.sB[0]=0; a.bscz[0][0]=1.f; a.kst[0]=Kn/16;
    a.lda=Cn; a.nseg=1; a.sA=(long)Vn*Cn; a.sC=(long)Vn*Cn;
    a.bias=bl; a.act=0; a.terms=3;
    k_gemm<<<dim3(32,Bn,1),256>>>(a); }
}

// round 12
// speedup vs baseline: 2.1856x; 1.0173x over previous
#include <cuda_runtime.h>
#include <cuda_fp16.h>
#include <cstdint>

#define Bn 4
#define Vn 4096
#define Kn 128
#define Cn 128
#define NS 32

// ---- scratch (allocation-free rule: __device__ globals) ----
__device__ float g_GXE[Bn*Vn*Kn], g_GYE[Bn*Vn*Kn];
__device__ float g_x[Bn*Vn*Cn], g_xd[Bn*Vn*Cn], g_gx[Bn*Vn*Cn], g_gy[Bn*Vn*Cn];
__device__ float g_Sp[Bn*NS*Kn*Cn], g_D[Bn*Kn*Cn];

// A tiles: [128 m][16 k] halves, row stride 48B -> conflict-free ldmatrix
// B tiles: [16 k][128 n] halves, row stride 272B
#define SA_B 48
#define SB_B 272
// one staging buffer set: Ah@0 (6144), Al@6144, Bh@12288 (4352), Bl@16640
#define SETSZ 20992
#define O_AL 6144
#define O_BH 12288
#define O_BL 16640

// k_mlp dynamic smem map: two staging sets, then resident A-format tiles
#define S_T1H 41984
#define S_T1L (S_T1H+34816)
#define S_T2H (S_T1L+34816)
#define S_T2L (S_T2H+34816)
#define SMEM_MLP (S_T2L+34816)

__device__ __forceinline__ uint32_t s2u(const void* p){
  uint32_t a; asm("{ .reg .u64 t; cvta.to.shared.u64 t, %1; cvt.u32.u64 %0, t; }":"=r"(a):"l"(p));
  return a;
}
__device__ __forceinline__ uint32_t packh(__half a, __half b){
  __half2 t=__halves2half2(a,b); return *(uint32_t*)&t;
}
__device__ __forceinline__ void split2(float x, __half& h, __half& l){
  h=__float2half_rn(x); l=__float2half_rn(x-__half2float(h));
}
__device__ __forceinline__ void ldsm4(uint32_t a, uint32_t* r){
  asm volatile("ldmatrix.sync.aligned.m8n8.x4.shared.b16 {%0,%1,%2,%3},[%4];"
    :"=r"(r[0]),"=r"(r[1]),"=r"(r[2]),"=r"(r[3]):"r"(a));
}
__device__ __forceinline__ void ldsm4t(uint32_t a, uint32_t* r){
  asm volatile("ldmatrix.sync.aligned.m8n8.x4.trans.shared.b16 {%0,%1,%2,%3},[%4];"
    :"=r"(r[0]),"=r"(r[1]),"=r"(r[2]),"=r"(r[3]):"r"(a));
}
__device__ __forceinline__ void mma16(float* d, const uint32_t* a, uint32_t b0, uint32_t b1){
  asm volatile("mma.sync.aligned.m16n8k16.row.col.f32.f16.f16.f32 "
    "{%0,%1,%2,%3},{%4,%5,%6,%7},{%8,%9},{%0,%1,%2,%3};"
    : "+f"(d[0]),"+f"(d[1]),"+f"(d[2]),"+f"(d[3])
    : "r"(a[0]),"r"(a[1]),"r"(a[2]),"r"(a[3]),"r"(b0),"r"(b1));
}
__device__ __forceinline__ void zacc(float (&a)[2][8][4]){
#pragma unroll
  for(int i=0;i<2;i++)
#pragma unroll
  for(int j=0;j<8;j++)
#pragma unroll
  for(int q=0;q<4;q++) a[i][j][q]=0.f;
}

// ---- gmem->regs prefetch ----
__device__ __forceinline__ void ldA(const float* A, int lda, int tid, float4* r){
#pragma unroll
  for(int i=0;i<2;i++){ int idx=tid+i*256;
    r[i]=*(const float4*)(A+(size_t)(idx>>2)*lda+((idx&3)<<2)); }
}
__device__ __forceinline__ void ldB(const float* S, int lds, int tid, float4* r){
#pragma unroll
  for(int i=0;i<2;i++){ int idx=tid+i*256;
    r[i]=*(const float4*)(S+(size_t)(idx&15)*lds+(((idx>>4)&31)<<2)); }
}
// ---- regs->smem staging with fp16 hi/lo split ----
__device__ __forceinline__ void stA(char* H, char* L, const float4* r, int tid){
#pragma unroll
  for(int i=0;i<2;i++){
    int idx=tid+i*256; int m=idx>>2, kq=(idx&3)<<2;
    float4 v=r[i];
    __half h0,h1,h2,h3,l0,l1,l2,l3;
    split2(v.x,h0,l0); split2(v.y,h1,l1); split2(v.z,h2,l2); split2(v.w,h3,l3);
    *(uint2*)(H+m*SA_B+kq*2)=make_uint2(packh(h0,h1),packh(h2,h3));
    *(uint2*)(L+m*SA_B+kq*2)=make_uint2(packh(l0,l1),packh(l2,l3));
  }
}
__device__ __forceinline__ void stB(char* H, char* L, const float4* r, int tid,
                                    const float* si){
#pragma unroll
  for(int i=0;i<2;i++){
    int idx=tid+i*256; int k=idx&15, nq=((idx>>4)&31)<<2;
    float s=si[i];
    float4 v=r[i];
    __half h0,h1,h2,h3,l0,l1,l2,l3;
    split2(v.x*s,h0,l0); split2(v.y*s,h1,l1); split2(v.z*s,h2,l2); split2(v.w*s,h3,l3);
    *(uint2*)(H+k*SB_B+nq*2)=make_uint2(packh(h0,h1),packh(h2,h3));
    *(uint2*)(L+k*SB_B+nq*2)=make_uint2(packh(l0,l1),packh(l2,l3));
  }
}
// transposed A staging (for k_spec: A = E^T): source [16 k][128 m] -> A layout [m][k]
__device__ __forceinline__ void stTA(char* H, char* L, const float4* r, int tid){
#pragma unroll
  for(int i=0;i<2;i++){
    int idx=tid+i*256; int k=idx&15, nq=((idx>>4)&31)<<2;
    float4 v=r[i];
    float e[4]={v.x,v.y,v.z,v.w};
#pragma unroll
    for(int j=0;j<4;j++){
      __half h,l; split2(e[j],h,l);
      *(__half*)(H+(nq+j)*SA_B+k*2)=h;
      *(__half*)(L+(nq+j)*SA_B+k*2)=l;
    }
  }
}

// one 16-deep K step: double-fp16, warp tile 32x64, 8 warps -> 128x128
// three=1: ah*bh + ah*bl + al*bh; three=0: ah*bh + al*bh
__device__ __forceinline__ void gstep(uint32_t aH, uint32_t aL, int sA,
                                      uint32_t bH, uint32_t bL,
                                      float (&acc)[2][8][4], int wm,int wn,int lane,
                                      int three){
  int lr=lane&15, lc=lane>>4;
  uint32_t ah[2][4], al[2][4];
#pragma unroll
  for(int mt=0;mt<2;mt++){
    uint32_t off=(uint32_t)((wm*32+mt*16+lr)*sA+lc*16);
    ldsm4(aH+off, ah[mt]); ldsm4(aL+off, al[mt]);
  }
#pragma unroll
  for(int bt=0;bt<4;bt++){
    uint32_t bh[4], bl[4];
    uint32_t off=(uint32_t)(lr*SB_B+(wn*64+bt*16+lc*8)*2);
    ldsm4t(bH+off, bh);
    if(three) ldsm4t(bL+off, bl);
#pragma unroll
    for(int j=0;j<2;j++){
      int nt=bt*2+j;
#pragma unroll
      for(int mt=0;mt<2;mt++){
        mma16(acc[mt][nt], ah[mt], bh[2*j], bh[2*j+1]);
        if(three) mma16(acc[mt][nt], ah[mt], bl[2*j], bl[2*j+1]);
        mma16(acc[mt][nt], al[mt], bh[2*j], bh[2*j+1]);
      }
    }
  }
}

struct GArgs {
  const float* A[3][3];   // [z][seg]
  float* C[3];            // [z]
  const float* Bs[3]; long sB[3]; int kst[3];  // kst in 16-wide tiles
  float bscz[3][3];       // [z][seg]
  int lda, nseg;
  long sA, sC;
  const float* bias; const float* res; long sRes;
  int act;                // 1 = relu
  int terms;              // 3 or 2
};

__global__ void __launch_bounds__(256,2) k_gemm(GArgs ga){
  __shared__ __align__(16) char SBf[2][SETSZ];
  int tid=threadIdx.x, lane=tid&31, w=tid>>5, wm=w&3, wn=w>>2;
  uint32_t sb0=s2u(SBf[0]), sb1=s2u(SBf[1]);
  float acc[2][8][4]={};
  int mt=blockIdx.x, b=blockIdx.y, z=blockIdx.z;
  int three=(ga.terms==3);
  int T=0;
#pragma unroll
  for(int s=0;s<3;s++) if(s<ga.nseg) T+=ga.kst[s];
  int seg=0,k0=0;
  const float* As   = ga.A[z][0] + (size_t)b*ga.sA + (size_t)mt*128*ga.lda;
  const float* Bsrc = ga.Bs[0]   + (size_t)b*ga.sB[0];
  float sc = ga.bscz[z][0];
  float4 ra[2], rb[2]; float si[2];
  ldA(As, ga.lda, tid, ra);
  ldB(Bsrc, Cn, tid, rb);
  si[0]=si[1]=sc;
  stA(SBf[0], SBf[0]+O_AL, ra, tid);
  stB(SBf[0]+O_BH, SBf[0]+O_BL, rb, tid, si);
  __syncthreads();
  for(int s=0;s<T;s++){
    int more=(s+1<T);
    if(more){
      k0++;
      if(k0==ga.kst[seg]){
        k0=0; seg++;
        As   = ga.A[z][seg] + (size_t)b*ga.sA + (size_t)mt*128*ga.lda;
        Bsrc = ga.Bs[seg]   + (size_t)b*ga.sB[seg];
        sc = ga.bscz[z][seg];
      }
      ldA(As + k0*16, ga.lda, tid, ra);
      ldB(Bsrc + (size_t)k0*16*Cn, Cn, tid, rb);
      si[0]=si[1]=sc;
    }
    uint32_t cb=(s&1)?sb1:sb0;
    gstep(cb, cb+O_AL, SA_B, cb+O_BH, cb+O_BL, acc, wm,wn,lane, three);
    if(more){
      char* nb=SBf[(s+1)&1];
      stA(nb, nb+O_AL, ra, tid);
      stB(nb+O_BH, nb+O_BL, rb, tid, si);
    }
    __syncthreads();
  }
  float* Cg = ga.C[z] + (size_t)b*ga.sC + (size_t)mt*128*Cn;
  const float* Rg = ga.res ? ga.res + (size_t)b*ga.sRes + (size_t)mt*128*Cn : nullptr;
  int er=lane>>2, ec=lane&3;
#pragma unroll
  for(int m2=0;m2<2;m2++)
#pragma unroll
  for(int nt=0;nt<8;nt++){
    int row=wm*32+m2*16+er, col=wn*64+nt*8+2*ec;
    float* av=acc[m2][nt];
#pragma unroll
    for(int rr=0;rr<2;rr++){
      int R=row+rr*8;
      float v0=av[rr*2], v1=av[rr*2+1];
      if(ga.bias){ v0+=ga.bias[col]; v1+=ga.bias[col+1]; }
      if(ga.act==1){ v0=fmaxf(v0,0.f); v1=fmaxf(v1,0.f); }
      if(Rg){ v0+=Rg[(size_t)R*Cn+col]; v1+=Rg[(size_t)R*Cn+col+1]; }
      Cg[(size_t)R*Cn+col]=v0; Cg[(size_t)R*Cn+col+1]=v1;
    }
  }
}

// ---- fused per-block MLP: br/bi -> gfeat -> h0 -> h1 -> h2(+residual) ----
struct MSeg { const float* A; const float* Bw; float sc; int resOff; }; // A==null -> resident

// double-buffered, single-sync-per-step; all segments are 8 steps (K=128)
__device__ __forceinline__ void ugemm(char* sm, const MSeg* segs, int nseg,
    float (&acc)[2][8][4], int tid, int wm, int wn, int lane){
  uint32_t sb=s2u(sm);
  int TT=nseg*8;
  float4 ra[2], rb[2]; float si[2];
  {
    const MSeg* c0=&segs[0];
    if(c0->A) ldA(c0->A, Cn, tid, ra);
    ldB(c0->Bw, Cn, tid, rb);
    si[0]=si[1]=c0->sc;
    if(c0->A) stA(sm, sm+O_AL, ra, tid);
    stB(sm+O_BH, sm+O_BL, rb, tid, si);
  }
  __syncthreads();
  for(int g=0; g<TT; g++){
    const MSeg* cur=&segs[g>>3]; int ks=g&7;
    const MSeg* nxt=(g+1<TT)? &segs[(g+1)>>3] : nullptr;
    int nks=(g+1)&7;
    if(nxt){
      if(nxt->A) ldA(nxt->A + nks*16, Cn, tid, ra);
      ldB(nxt->Bw + (size_t)nks*16*Cn, Cn, tid, rb);
      si[0]=si[1]=nxt->sc;
    }
    uint32_t cb=sb+(uint32_t)(g&1)*SETSZ;
    if(cur->A)
      gstep(cb, cb+O_AL, SA_B, cb+O_BH, cb+O_BL, acc, wm, wn, lane, 1);
    else
      gstep(sb+cur->resOff+ks*32, sb+cur->resOff+34816+ks*32, 272,
            cb+O_BH, cb+O_BL, acc, wm, wn, lane, 1);
    if(nxt){
      char* nb=sm+((g+1)&1)*SETSZ;
      if(nxt->A) stA(nb, nb+O_AL, ra, tid);
      stB(nb+O_BH, nb+O_BL, rb, tid, si);
    }
    __syncthreads();
  }
}

__device__ __forceinline__ void epi_split(char* sm, int Hoff, int Loff,
    float (&acc)[2][8][4], const float* bias, int relu, int wm, int wn, int lane){
  int er=lane>>2, ec=lane&3;
#pragma unroll
  for(int m2=0;m2<2;m2++)
#pragma unroll
  for(int nt=0;nt<8;nt++){
    int row=wm*32+m2*16+er, col=wn*64+nt*8+2*ec;
#pragma unroll
    for(int rr=0;rr<2;rr++){
      int R=row+rr*8;
      float v0=acc[m2][nt][rr*2]+bias[col], v1=acc[m2][nt][rr*2+1]+bias[col+1];
      if(relu){ v0=fmaxf(v0,0.f); v1=fmaxf(v1,0.f); }
      __half h0v,l0v,h1v,l1v; split2(v0,h0v,l0v); split2(v1,h1v,l1v);
      *(uint32_t*)(sm+Hoff+R*272+col*2)=packh(h0v,h1v);
      *(uint32_t*)(sm+Loff+R*272+col*2)=packh(l0v,l1v);
    }
  }
}

__global__ void __launch_bounds__(256) k_mlp(const float* Are,const float* Aim,
    const float* W0,const float* b0,const float* W1,const float* b1,
    const float* W2,const float* b2){
  extern __shared__ char sm[];
  int tid=threadIdx.x, lane=tid&31, w=tid>>5, wm=w&3, wn=w>>2;
  int mt=blockIdx.x, b=blockIdx.y;
  size_t rowoff=(size_t)b*Vn*Cn+(size_t)mt*128*Cn;
  const float* gx=g_gx+rowoff; const float* gy=g_gy+rowoff;
  const float* xd=g_xd+rowoff;
  float* xr=g_x+rowoff;
  float acc[2][8][4];
  float brg[2][8][4];           // br kept in registers (same thread reads back)
  int er=lane>>2, ec=lane&3;

  // br = gx@Are - gy@Aim  -> registers
  zacc(acc);
  { MSeg s[2]={{gx,Are,1.f,-1},{gy,Aim,-1.f,-1}}; ugemm(sm,s,2,acc,tid,wm,wn,lane); }
#pragma unroll
  for(int m2=0;m2<2;m2++)
#pragma unroll
  for(int nt=0;nt<8;nt++)
#pragma unroll
  for(int q=0;q<4;q++) brg[m2][nt][q]=acc[m2][nt][q];
  // bi = gy@Are + gx@Aim
  zacc(acc);
  { MSeg s[2]={{gy,Are,1.f,-1},{gx,Aim,1.f,-1}}; ugemm(sm,s,2,acc,tid,wm,wn,lane); }
  // gfeat = tanh(gx*br + gy*bi) -> A-format split at T1
#pragma unroll
  for(int m2=0;m2<2;m2++)
#pragma unroll
  for(int nt=0;nt<8;nt++){
    int row=wm*32+m2*16+er, col=wn*64+nt*8+2*ec;
#pragma unroll
    for(int rr=0;rr<2;rr++){
      int R=row+rr*8;
      float gx0=gx[(size_t)R*Cn+col], gx1=gx[(size_t)R*Cn+col+1];
      float gy0=gy[(size_t)R*Cn+col], gy1=gy[(size_t)R*Cn+col+1];
      float v0=tanhf(gx0*brg[m2][nt][rr*2]+gy0*acc[m2][nt][rr*2]);
      float v1=tanhf(gx1*brg[m2][nt][rr*2+1]+gy1*acc[m2][nt][rr*2+1]);
      __half h0v,l0v,h1v,l1v; split2(v0,h0v,l0v); split2(v1,h1v,l1v);
      *(uint32_t*)(sm+S_T1H+R*272+col*2)=packh(h0v,h1v);
      *(uint32_t*)(sm+S_T1L+R*272+col*2)=packh(l0v,l1v);
    }
  }
  __syncthreads();
  // h0 = relu([x|xd|gf]@W0 + b0) -> T2
  zacc(acc);
  { MSeg s[3]={{xr,W0,1.f,-1},{xd,W0+128*Cn,1.f,-1},{nullptr,W0+256*Cn,1.f,S_T1H}};
    ugemm(sm,s,3,acc,tid,wm,wn,lane); }
  epi_split(sm,S_T2H,S_T2L,acc,b0,1,wm,wn,lane);
  __syncthreads();
  // h1 = relu(h0@W1 + b1) -> T1
  zacc(acc);
  { MSeg s[1]={{nullptr,W1,1.f,S_T2H}}; ugemm(sm,s,1,acc,tid,wm,wn,lane); }
  epi_split(sm,S_T1H,S_T1L,acc,b1,1,wm,wn,lane);
  __syncthreads();
  // x += h1@W2 + b2
  zacc(acc);
  { MSeg s[1]={{nullptr,W2,1.f,S_T1H}}; ugemm(sm,s,1,acc,tid,wm,wn,lane); }
#pragma unroll
  for(int m2=0;m2<2;m2++)
#pragma unroll
  for(int nt=0;nt<8;nt++){
    int row=wm*32+m2*16+er, col=wn*64+nt*8+2*ec;
#pragma unroll
    for(int rr=0;rr<2;rr++){
      int R=row+rr*8;
      float v0=acc[m2][nt][rr*2]+b2[col]+xr[(size_t)R*Cn+col];
      float v1=acc[m2][nt][rr*2+1]+b2[col+1]+xr[(size_t)R*Cn+col+1];
      xr[(size_t)R*Cn+col]=v0; xr[(size_t)R*Cn+col+1]=v1;
    }
  }
}

// x_spec split-K partials: Sp[b,sp] = E[v0:v0+V/NS]^T @ (x*mass)[v0:v0+V/NS]
__global__ void __launch_bounds__(256,2) k_spec(const float* E, const float* mass){
  __shared__ __align__(16) char SBf[2][SETSZ];
  int tid=threadIdx.x, lane=tid&31, w=tid>>5, wm=w&3, wn=w>>2;
  uint32_t sb0=s2u(SBf[0]), sb1=s2u(SBf[1]);
  float acc[2][8][4]={};
  int b=blockIdx.x, sp=blockIdx.y;
  const float* Eb=E+(size_t)b*Vn*Kn;
  const float* Xb=g_x+(size_t)b*Vn*Cn;
  const float* Mb=mass+(size_t)b*Vn;
  int v0=sp*(Vn/NS);
  const int T=(Vn/NS)/16;
  float4 ra[2], rb[2]; float ms[2];
  ldB(Eb+(size_t)v0*Kn, Kn, tid, ra);
  ldB(Xb+(size_t)v0*Cn, Cn, tid, rb);
#pragma unroll
  for(int i=0;i<2;i++){ int idx=tid+i*256; ms[i]=Mb[v0+(idx&15)]; }
  stTA(SBf[0], SBf[0]+O_AL, ra, tid);
  stB(SBf[0]+O_BH, SBf[0]+O_BL, rb, tid, ms);
  __syncthreads();
  for(int s=0;s<T;s++){
    int more=(s+1<T);
    if(more){
      int v=v0+(s+1)*16;
      ldB(Eb+(size_t)v*Kn, Kn, tid, ra);
      ldB(Xb+(size_t)v*Cn, Cn, tid, rb);
#pragma unroll
      for(int i=0;i<2;i++){ int idx=tid+i*256; ms[i]=Mb[v+(idx&15)]; }
    }
    uint32_t cb=(s&1)?sb1:sb0;
    gstep(cb, cb+O_AL, SA_B, cb+O_BH, cb+O_BL, acc, wm,wn,lane, 1);
    if(more){
      char* nb=SBf[(s+1)&1];
      stTA(nb, nb+O_AL, ra, tid);
      stB(nb+O_BH, nb+O_BL, rb, tid, ms);
    }
    __syncthreads();
  }
  float* Cg=g_Sp+(size_t)(b*NS+sp)*Kn*Cn;
  int er=lane>>2, ec=lane&3;
#pragma unroll
  for(int m2=0;m2<2;m2++)
#pragma unroll
  for(int nt=0;nt<8;nt++){
    int row=wm*32+m2*16+er, col=wn*64+nt*8+2*ec;
    float* av=acc[m2][nt];
    *(float2*)&Cg[(size_t)row*Cn+col]     = make_float2(av[0],av[1]);
    *(float2*)&Cg[(size_t)(row+8)*Cn+col] = make_float2(av[2],av[3]);
  }
}

// reduce NS split partials + apply diffusion coefficients
__global__ void k_coef(const float* evals, const float* t, int blk){
  int b=blockIdx.x;
  int base=blockIdx.y*1024;
  const float* tb=t+blk*Cn;
  for(int i=threadIdx.x; i<1024; i+=blockDim.x){
    int idx=base+i;
    int k=idx>>7, c=idx&127;
    float s=0.f;
#pragma unroll
    for(int sp=0;sp<NS;sp++) s+=g_Sp[(size_t)(b*NS+sp)*Kn*Cn+idx];
    g_D[(size_t)b*Kn*Cn+idx]=expf(-evals[b*Kn+k]*fmaxf(tb[c],1e-8f))*s;
  }
}

// x = x_in @ Wf + bf  (K=16, tiny)
__global__ void k_x0(const float* xi, const float* Wf, const float* bf){
  __shared__ float w[16*128];
  __shared__ float xs[16][17];
  int tid=threadIdx.x;
  for(int i=tid;i<2048;i+=128) w[i]=Wf[i];
  int r0=blockIdx.x*16;
  for(int i=tid;i<256;i+=128) xs[i>>4][i&15]=xi[(size_t)r0*16+i];
  __syncthreads();
  float bv=bf[tid];
#pragma unroll
  for(int rr=0;rr<16;rr++){
    float s=bv;
#pragma unroll
    for(int k=0;k<16;k++) s+=xs[rr][k]*w[k*128+tid];
    g_x[(size_t)(r0+rr)*Cn+tid]=s;
  }
}

extern "C" void kernel_launch(void* const* d_in, const int* in_sizes, int n_in,
                              void* d_out, int out_size){
  const float *x_in=(const float*)d_in[0], *mass=(const float*)d_in[1],
    *evals=(const float*)d_in[2], *evecs=(const float*)d_in[3],
    *gradX=(const float*)d_in[4], *gradY=(const float*)d_in[5],
    *Wf=(const float*)d_in[6], *bf=(const float*)d_in[7],
    *Wl=(const float*)d_in[8], *bl=(const float*)d_in[9],
    *t=(const float*)d_in[10], *Are=(const float*)d_in[11], *Aim=(const float*)d_in[12],
    *W0=(const float*)d_in[13], *b0=(const float*)d_in[14],
    *W1=(const float*)d_in[15], *b1=(const float*)d_in[16],
    *W2=(const float*)d_in[17], *b2=(const float*)d_in[18];
  float* out=(float*)d_out;

  cudaFuncSetAttribute(k_mlp, cudaFuncAttributeMaxDynamicSharedMemorySize, SMEM_MLP);

  float *GXEp,*GYEp,*xp,*xdp,*gxp,*gyp,*Dp;
  cudaGetSymbolAddress((void**)&GXEp,g_GXE); cudaGetSymbolAddress((void**)&GYEp,g_GYE);
  cudaGetSymbolAddress((void**)&xp,g_x);     cudaGetSymbolAddress((void**)&xdp,g_xd);
  cudaGetSymbolAddress((void**)&gxp,g_gx);   cudaGetSymbolAddress((void**)&gyp,g_gy);
  cudaGetSymbolAddress((void**)&Dp,g_D);

  // precompute GXE = gradX@evecs, GYE = gradY@evecs (block-invariant)
  // 2-term split: A (gradX/gradY) exact hi+lo, B (evecs) hi only
  { GArgs a{}; a.A[0][0]=gradX; a.A[1][0]=gradY; a.C[0]=GXEp; a.C[1]=GYEp;
    a.Bs[0]=evecs; a.sB[0]=(long)Vn*Kn; a.bscz[0][0]=1.f; a.bscz[1][0]=1.f;
    a.kst[0]=Vn/16; a.lda=Vn; a.nseg=1; a.sA=(long)Vn*Vn; a.sC=(long)Vn*Kn; a.act=0;
    a.terms=2;
    k_gemm<<<dim3(32,Bn,2),256>>>(a); }

  k_x0<<<Bn*Vn/16,128>>>(x_in,Wf,bf);

  for(int i=0;i<4;i++){
    k_spec<<<dim3(Bn,NS),256>>>(evecs,mass);
    k_coef<<<dim3(Bn,16),256>>>(evals,t,i);
    // x_diff = E@D, gx = GXE@D, gy = GYE@D
    { GArgs a{}; a.A[0][0]=evecs; a.A[1][0]=GXEp; a.A[2][0]=GYEp;
      a.C[0]=xdp; a.C[1]=gxp; a.C[2]=gyp;
      a.Bs[0]=Dp; a.sB[0]=(long)Kn*Cn;
      a.bscz[0][0]=1.f; a.bscz[1][0]=1.f; a.bscz[2][0]=1.f;
      a.kst[0]=Kn/16; a.lda=Kn; a.nseg=1; a.sA=(long)Vn*Kn; a.sC=(long)Vn*Cn; a.act=0;
      a.terms=3;
      k_gemm<<<dim3(32,Bn,3),256>>>(a); }
    // fused: br/bi -> gfeat -> h0 -> h1 -> x += h2
    k_mlp<<<dim3(32,Bn),256,SMEM_MLP>>>(
        Are+(size_t)i*Cn*Cn, Aim+(size_t)i*Cn*Cn,
        W0+(size_t)i*384*Cn, b0+(size_t)i*Cn,
        W1+(size_t)i*Cn*Cn,  b1+(size_t)i*Cn,
        W2+(size_t)i*Cn*Cn,  b2+(size_t)i*Cn);
  }
  // out = x @ Wl + bl
  { GArgs a{}; a.A[0][0]=xp; a.C[0]=out;
    a.Bs[0]=Wl; a.sB[0]=0; a.bscz[0][0]=1.f; a.kst[0]=Kn/16;
    a.lda=Cn; a.nseg=1; a.sA=(long)Vn*Cn; a.sC=(long)Vn*Cn;
    a.bias=bl; a.act=0; a.terms=3;
    k_gemm<<<dim3(32,Bn,1),256>>>(a); }
}

// round 14
// speedup vs baseline: 2.1943x; 1.0040x over previous
#include <cuda_runtime.h>
#include <cuda_fp16.h>
#include <cstdint>

#define Bn 4
#define Vn 4096
#define Kn 128
#define Cn 128
#define NS 32

// ---- scratch (allocation-free rule: __device__ globals) ----
__device__ float g_GXE[Bn*Vn*Kn], g_GYE[Bn*Vn*Kn];
__device__ float g_x[Bn*Vn*Cn], g_xd[Bn*Vn*Cn], g_gx[Bn*Vn*Cn], g_gy[Bn*Vn*Cn];
__device__ float g_Sp[Bn*NS*Kn*Cn], g_D[Bn*Kn*Cn];

#define SA_B 48
#define SB_B 272
#define SETSZ 20992
#define O_AL 6144
#define O_BH 12288
#define O_BL 16640

#define S_T1H 41984
#define S_T1L (S_T1H+34816)
#define S_T2H (S_T1L+34816)
#define S_T2L (S_T2H+34816)
#define SMEM_MLP (S_T2L+34816)

__device__ __forceinline__ uint32_t s2u(const void* p){
  uint32_t a; asm("{ .reg .u64 t; cvta.to.shared.u64 t, %1; cvt.u32.u64 %0, t; }":"=r"(a):"l"(p));
  return a;
}
__device__ __forceinline__ uint32_t packh(__half a, __half b){
  __half2 t=__halves2half2(a,b); return *(uint32_t*)&t;
}
__device__ __forceinline__ void split2(float x, __half& h, __half& l){
  h=__float2half_rn(x); l=__float2half_rn(x-__half2float(h));
}
__device__ __forceinline__ void ldsm4(uint32_t a, uint32_t* r){
  asm volatile("ldmatrix.sync.aligned.m8n8.x4.shared.b16 {%0,%1,%2,%3},[%4];"
    :"=r"(r[0]),"=r"(r[1]),"=r"(r[2]),"=r"(r[3]):"r"(a));
}
__device__ __forceinline__ void ldsm4t(uint32_t a, uint32_t* r){
  asm volatile("ldmatrix.sync.aligned.m8n8.x4.trans.shared.b16 {%0,%1,%2,%3},[%4];"
    :"=r"(r[0]),"=r"(r[1]),"=r"(r[2]),"=r"(r[3]):"r"(a));
}
__device__ __forceinline__ void mma16(float* d, const uint32_t* a, uint32_t b0, uint32_t b1){
  asm volatile("mma.sync.aligned.m16n8k16.row.col.f32.f16.f16.f32 "
    "{%0,%1,%2,%3},{%4,%5,%6,%7},{%8,%9},{%0,%1,%2,%3};"
    : "+f"(d[0]),"+f"(d[1]),"+f"(d[2]),"+f"(d[3])
    : "r"(a[0]),"r"(a[1]),"r"(a[2]),"r"(a[3]),"r"(b0),"r"(b1));
}
__device__ __forceinline__ void zacc(float (&a)[2][8][4]){
#pragma unroll
  for(int i=0;i<2;i++)
#pragma unroll
  for(int j=0;j<8;j++)
#pragma unroll
  for(int q=0;q<4;q++) a[i][j][q]=0.f;
}

// ---- gmem->regs prefetch ----
__device__ __forceinline__ void ldA(const float* A, int lda, int tid, float4* r){
#pragma unroll
  for(int i=0;i<2;i++){ int idx=tid+i*256;
    r[i]=*(const float4*)(A+(size_t)(idx>>2)*lda+((idx&3)<<2)); }
}
__device__ __forceinline__ void ldB(const float* S, int lds, int tid, float4* r){
#pragma unroll
  for(int i=0;i<2;i++){ int idx=tid+i*256;
    r[i]=*(const float4*)(S+(size_t)(idx&15)*lds+(((idx>>4)&31)<<2)); }
}
// ---- regs->smem staging with fp16 hi/lo split ----
__device__ __forceinline__ void stA(char* H, char* L, const float4* r, int tid){
#pragma unroll
  for(int i=0;i<2;i++){
    int idx=tid+i*256; int m=idx>>2, kq=(idx&3)<<2;
    float4 v=r[i];
    __half h0,h1,h2,h3,l0,l1,l2,l3;
    split2(v.x,h0,l0); split2(v.y,h1,l1); split2(v.z,h2,l2); split2(v.w,h3,l3);
    *(uint2*)(H+m*SA_B+kq*2)=make_uint2(packh(h0,h1),packh(h2,h3));
    *(uint2*)(L+m*SA_B+kq*2)=make_uint2(packh(l0,l1),packh(l2,l3));
  }
}
__device__ __forceinline__ void stB(char* H, char* L, const float4* r, int tid,
                                    const float* si){
#pragma unroll
  for(int i=0;i<2;i++){
    int idx=tid+i*256; int k=idx&15, nq=((idx>>4)&31)<<2;
    float s=si[i];
    float4 v=r[i];
    __half h0,h1,h2,h3,l0,l1,l2,l3;
    split2(v.x*s,h0,l0); split2(v.y*s,h1,l1); split2(v.z*s,h2,l2); split2(v.w*s,h3,l3);
    *(uint2*)(H+k*SB_B+nq*2)=make_uint2(packh(h0,h1),packh(h2,h3));
    *(uint2*)(L+k*SB_B+nq*2)=make_uint2(packh(l0,l1),packh(l2,l3));
  }
}
// transposed A staging (k_spec: A = E^T): source [16 k][128 m] -> A layout [m][k]
__device__ __forceinline__ void stTA(char* H, char* L, const float4* r, int tid){
#pragma unroll
  for(int i=0;i<2;i++){
    int idx=tid+i*256; int k=idx&15, nq=((idx>>4)&31)<<2;
    float4 v=r[i];
    float e[4]={v.x,v.y,v.z,v.w};
#pragma unroll
    for(int j=0;j<4;j++){
      __half h,l; split2(e[j],h,l);
      *(__half*)(H+(nq+j)*SA_B+k*2)=h;
      *(__half*)(L+(nq+j)*SA_B+k*2)=l;
    }
  }
}

// one 16-deep K step: double-fp16, warp tile 32x64, 8 warps -> 128x128
// TERM-MAJOR mma order: dependent mmas on the same accumulator are separated
// by 3 independent mmas (RAW-latency hiding).
__device__ __forceinline__ void gstep(uint32_t aH, uint32_t aL, int sA,
                                      uint32_t bH, uint32_t bL,
                                      float (&acc)[2][8][4], int wm,int wn,int lane,
                                      int three){
  int lr=lane&15, lc=lane>>4;
  uint32_t ah[2][4], al[2][4];
#pragma unroll
  for(int mt=0;mt<2;mt++){
    uint32_t off=(uint32_t)((wm*32+mt*16+lr)*sA+lc*16);
    ldsm4(aH+off, ah[mt]); ldsm4(aL+off, al[mt]);
  }
#pragma unroll
  for(int bt=0;bt<4;bt++){
    uint32_t bh[4], bl[4];
    uint32_t off=(uint32_t)(lr*SB_B+(wn*64+bt*16+lc*8)*2);
    ldsm4t(bH+off, bh);
    if(three) ldsm4t(bL+off, bl);
    // term 1: ah*bh over 4 independent accumulators
#pragma unroll
    for(int j=0;j<2;j++)
#pragma unroll
      for(int mt=0;mt<2;mt++)
        mma16(acc[mt][bt*2+j], ah[mt], bh[2*j], bh[2*j+1]);
    // term 2: ah*bl
    if(three){
#pragma unroll
      for(int j=0;j<2;j++)
#pragma unroll
        for(int mt=0;mt<2;mt++)
          mma16(acc[mt][bt*2+j], ah[mt], bl[2*j], bl[2*j+1]);
    }
    // term 3: al*bh
#pragma unroll
    for(int j=0;j<2;j++)
#pragma unroll
      for(int mt=0;mt<2;mt++)
        mma16(acc[mt][bt*2+j], al[mt], bh[2*j], bh[2*j+1]);
  }
}

struct GArgs {
  const float* A[3][3];
  float* C[3];
  const float* Bs[3]; long sB[3]; int kst[3];
  float bscz[3][3];
  int lda, nseg;
  long sA, sC;
  const float* bias; const float* res; long sRes;
  int act;
  int terms;
};

__global__ void __launch_bounds__(256,2) k_gemm(GArgs ga){
  __shared__ __align__(16) char SBf[2][SETSZ];
  int tid=threadIdx.x, lane=tid&31, w=tid>>5, wm=w&3, wn=w>>2;
  uint32_t sb0=s2u(SBf[0]), sb1=s2u(SBf[1]);
  float acc[2][8][4]={};
  int mt=blockIdx.x, b=blockIdx.y, z=blockIdx.z;
  int three=(ga.terms==3);
  int T=0;
#pragma unroll
  for(int s=0;s<3;s++) if(s<ga.nseg) T+=ga.kst[s];
  int seg=0,k0=0;
  const float* As   = ga.A[z][0] + (size_t)b*ga.sA + (size_t)mt*128*ga.lda;
  const float* Bsrc = ga.Bs[0]   + (size_t)b*ga.sB[0];
  float sc = ga.bscz[z][0];
  float4 ra[2], rb[2]; float si[2];
  ldA(As, ga.lda, tid, ra);
  ldB(Bsrc, Cn, tid, rb);
  si[0]=si[1]=sc;
  stA(SBf[0], SBf[0]+O_AL, ra, tid);
  stB(SBf[0]+O_BH, SBf[0]+O_BL, rb, tid, si);
  __syncthreads();
  for(int s=0;s<T;s++){
    int more=(s+1<T);
    if(more){
      k0++;
      if(k0==ga.kst[seg]){
        k0=0; seg++;
        As   = ga.A[z][seg] + (size_t)b*ga.sA + (size_t)mt*128*ga.lda;
        Bsrc = ga.Bs[seg]   + (size_t)b*ga.sB[seg];
        sc = ga.bscz[z][seg];
      }
      ldA(As + k0*16, ga.lda, tid, ra);
      ldB(Bsrc + (size_t)k0*16*Cn, Cn, tid, rb);
      si[0]=si[1]=sc;
    }
    uint32_t cb=(s&1)?sb1:sb0;
    gstep(cb, cb+O_AL, SA_B, cb+O_BH, cb+O_BL, acc, wm,wn,lane, three);
    if(more){
      char* nb=SBf[(s+1)&1];
      stA(nb, nb+O_AL, ra, tid);
      stB(nb+O_BH, nb+O_BL, rb, tid, si);
    }
    __syncthreads();
  }
  float* Cg = ga.C[z] + (size_t)b*ga.sC + (size_t)mt*128*Cn;
  const float* Rg = ga.res ? ga.res + (size_t)b*ga.sRes + (size_t)mt*128*Cn : nullptr;
  int er=lane>>2, ec=lane&3;
#pragma unroll
  for(int m2=0;m2<2;m2++)
#pragma unroll
  for(int nt=0;nt<8;nt++){
    int row=wm*32+m2*16+er, col=wn*64+nt*8+2*ec;
    float* av=acc[m2][nt];
#pragma unroll
    for(int rr=0;rr<2;rr++){
      int R=row+rr*8;
      float v0=av[rr*2], v1=av[rr*2+1];
      if(ga.bias){ v0+=ga.bias[col]; v1+=ga.bias[col+1]; }
      if(ga.act==1){ v0=fmaxf(v0,0.f); v1=fmaxf(v1,0.f); }
      if(Rg){ v0+=Rg[(size_t)R*Cn+col]; v1+=Rg[(size_t)R*Cn+col+1]; }
      Cg[(size_t)R*Cn+col]=v0; Cg[(size_t)R*Cn+col+1]=v1;
    }
  }
}

// ---- fused per-block MLP ----
struct MSeg { const float* A; const float* Bw; float sc; int resOff; };

__device__ __forceinline__ void ugemm(char* sm, const MSeg* segs, int nseg,
    float (&acc)[2][8][4], int tid, int wm, int wn, int lane){
  uint32_t sb=s2u(sm);
  int TT=nseg*8;
  float4 ra[2], rb[2]; float si[2];
  {
    const MSeg* c0=&segs[0];
    if(c0->A) ldA(c0->A, Cn, tid, ra);
    ldB(c0->Bw, Cn, tid, rb);
    si[0]=si[1]=c0->sc;
    if(c0->A) stA(sm, sm+O_AL, ra, tid);
    stB(sm+O_BH, sm+O_BL, rb, tid, si);
  }
  __syncthreads();
  for(int g=0; g<TT; g++){
    const MSeg* cur=&segs[g>>3]; int ks=g&7;
    const MSeg* nxt=(g+1<TT)? &segs[(g+1)>>3] : nullptr;
    int nks=(g+1)&7;
    if(nxt){
      if(nxt->A) ldA(nxt->A + nks*16, Cn, tid, ra);
      ldB(nxt->Bw + (size_t)nks*16*Cn, Cn, tid, rb);
      si[0]=si[1]=nxt->sc;
    }
    uint32_t cb=sb+(uint32_t)(g&1)*SETSZ;
    if(cur->A)
      gstep(cb, cb+O_AL, SA_B, cb+O_BH, cb+O_BL, acc, wm, wn, lane, 1);
    else
      gstep(sb+cur->resOff+ks*32, sb+cur->resOff+34816+ks*32, 272,
            cb+O_BH, cb+O_BL, acc, wm, wn, lane, 1);
    if(nxt){
      char* nb=sm+((g+1)&1)*SETSZ;
      if(nxt->A) stA(nb, nb+O_AL, ra, tid);
      stB(nb+O_BH, nb+O_BL, rb, tid, si);
    }
    __syncthreads();
  }
}

__device__ __forceinline__ void epi_split(char* sm, int Hoff, int Loff,
    float (&acc)[2][8][4], const float* bias, int relu, int wm, int wn, int lane){
  int er=lane>>2, ec=lane&3;
#pragma unroll
  for(int m2=0;m2<2;m2++)
#pragma unroll
  for(int nt=0;nt<8;nt++){
    int row=wm*32+m2*16+er, col=wn*64+nt*8+2*ec;
#pragma unroll
    for(int rr=0;rr<2;rr++){
      int R=row+rr*8;
      float v0=acc[m2][nt][rr*2]+bias[col], v1=acc[m2][nt][rr*2+1]+bias[col+1];
      if(relu){ v0=fmaxf(v0,0.f); v1=fmaxf(v1,0.f); }
      __half h0v,l0v,h1v,l1v; split2(v0,h0v,l0v); split2(v1,h1v,l1v);
      *(uint32_t*)(sm+Hoff+R*272+col*2)=packh(h0v,h1v);
      *(uint32_t*)(sm+Loff+R*272+col*2)=packh(l0v,l1v);
    }
  }
}

__global__ void __launch_bounds__(256) k_mlp(const float* Are,const float* Aim,
    const float* W0,const float* b0,const float* W1,const float* b1,
    const float* W2,const float* b2){
  extern __shared__ char sm[];
  int tid=threadIdx.x, lane=tid&31, w=tid>>5, wm=w&3, wn=w>>2;
  int mt=blockIdx.x, b=blockIdx.y;
  size_t rowoff=(size_t)b*Vn*Cn+(size_t)mt*128*Cn;
  const float* gx=g_gx+rowoff; const float* gy=g_gy+rowoff;
  const float* xd=g_xd+rowoff;
  float* xr=g_x+rowoff;
  float acc[2][8][4];
  float brg[2][8][4];
  int er=lane>>2, ec=lane&3;

  // br = gx@Are - gy@Aim -> registers
  zacc(acc);
  { MSeg s[2]={{gx,Are,1.f,-1},{gy,Aim,-1.f,-1}}; ugemm(sm,s,2,acc,tid,wm,wn,lane); }
#pragma unroll
  for(int m2=0;m2<2;m2++)
#pragma unroll
  for(int nt=0;nt<8;nt++)
#pragma unroll
  for(int q=0;q<4;q++) brg[m2][nt][q]=acc[m2][nt][q];
  // bi = gy@Are + gx@Aim
  zacc(acc);
  { MSeg s[2]={{gy,Are,1.f,-1},{gx,Aim,1.f,-1}}; ugemm(sm,s,2,acc,tid,wm,wn,lane); }
  // gfeat = tanh(gx*br + gy*bi) -> A-format split at T1
#pragma unroll
  for(int m2=0;m2<2;m2++)
#pragma unroll
  for(int nt=0;nt<8;nt++){
    int row=wm*32+m2*16+er, col=wn*64+nt*8+2*ec;
#pragma unroll
    for(int rr=0;rr<2;rr++){
      int R=row+rr*8;
      float gx0=gx[(size_t)R*Cn+col], gx1=gx[(size_t)R*Cn+col+1];
      float gy0=gy[(size_t)R*Cn+col], gy1=gy[(size_t)R*Cn+col+1];
      float v0=tanhf(gx0*brg[m2][nt][rr*2]+gy0*acc[m2][nt][rr*2]);
      float v1=tanhf(gx1*brg[m2][nt][rr*2+1]+gy1*acc[m2][nt][rr*2+1]);
      __half h0v,l0v,h1v,l1v; split2(v0,h0v,l0v); split2(v1,h1v,l1v);
      *(uint32_t*)(sm+S_T1H+R*272+col*2)=packh(h0v,h1v);
      *(uint32_t*)(sm+S_T1L+R*272+col*2)=packh(l0v,l1v);
    }
  }
  __syncthreads();
  // h0 = relu([x|xd|gf]@W0 + b0) -> T2
  zacc(acc);
  { MSeg s[3]={{xr,W0,1.f,-1},{xd,W0+128*Cn,1.f,-1},{nullptr,W0+256*Cn,1.f,S_T1H}};
    ugemm(sm,s,3,acc,tid,wm,wn,lane); }
  epi_split(sm,S_T2H,S_T2L,acc,b0,1,wm,wn,lane);
  __syncthreads();
  // h1 = relu(h0@W1 + b1) -> T1
  zacc(acc);
  { MSeg s[1]={{nullptr,W1,1.f,S_T2H}}; ugemm(sm,s,1,acc,tid,wm,wn,lane); }
  epi_split(sm,S_T1H,S_T1L,acc,b1,1,wm,wn,lane);
  __syncthreads();
  // x += h1@W2 + b2
  zacc(acc);
  { MSeg s[1]={{nullptr,W2,1.f,S_T1H}}; ugemm(sm,s,1,acc,tid,wm,wn,lane); }
#pragma unroll
  for(int m2=0;m2<2;m2++)
#pragma unroll
  for(int nt=0;nt<8;nt++){
    int row=wm*32+m2*16+er, col=wn*64+nt*8+2*ec;
#pragma unroll
    for(int rr=0;rr<2;rr++){
      int R=row+rr*8;
      float v0=acc[m2][nt][rr*2]+b2[col]+xr[(size_t)R*Cn+col];
      float v1=acc[m2][nt][rr*2+1]+b2[col+1]+xr[(size_t)R*Cn+col+1];
      xr[(size_t)R*Cn+col]=v0; xr[(size_t)R*Cn+col+1]=v1;
    }
  }
}

// x_spec split-K partials
__global__ void __launch_bounds__(256,2) k_spec(const float* E, const float* mass){
  __shared__ __align__(16) char SBf[2][SETSZ];
  int tid=threadIdx.x, lane=tid&31, w=tid>>5, wm=w&3, wn=w>>2;
  uint32_t sb0=s2u(SBf[0]), sb1=s2u(SBf[1]);
  float acc[2][8][4]={};
  int b=blockIdx.x, sp=blockIdx.y;
  const float* Eb=E+(size_t)b*Vn*Kn;
  const float* Xb=g_x+(size_t)b*Vn*Cn;
  const float* Mb=mass+(size_t)b*Vn;
  int v0=sp*(Vn/NS);
  const int T=(Vn/NS)/16;
  float4 ra[2], rb[2]; float ms[2];
  ldB(Eb+(size_t)v0*Kn, Kn, tid, ra);
  ldB(Xb+(size_t)v0*Cn, Cn, tid, rb);
#pragma unroll
  for(int i=0;i<2;i++){ int idx=tid+i*256; ms[i]=Mb[v0+(idx&15)]; }
  stTA(SBf[0], SBf[0]+O_AL, ra, tid);
  stB(SBf[0]+O_BH, SBf[0]+O_BL, rb, tid, ms);
  __syncthreads();
  for(int s=0;s<T;s++){
    int more=(s+1<T);
    if(more){
      int v=v0+(s+1)*16;
      ldB(Eb+(size_t)v*Kn, Kn, tid, ra);
      ldB(Xb+(size_t)v*Cn, Cn, tid, rb);
#pragma unroll
      for(int i=0;i<2;i++){ int idx=tid+i*256; ms[i]=Mb[v+(idx&15)]; }
    }
    uint32_t cb=(s&1)?sb1:sb0;
    gstep(cb, cb+O_AL, SA_B, cb+O_BH, cb+O_BL, acc, wm,wn,lane, 1);
    if(more){
      char* nb=SBf[(s+1)&1];
      stTA(nb, nb+O_AL, ra, tid);
      stB(nb+O_BH, nb+O_BL, rb, tid, ms);
    }
    __syncthreads();
  }
  float* Cg=g_Sp+(size_t)(b*NS+sp)*Kn*Cn;
  int er=lane>>2, ec=lane&3;
#pragma unroll
  for(int m2=0;m2<2;m2++)
#pragma unroll
  for(int nt=0;nt<8;nt++){
    int row=wm*32+m2*16+er, col=wn*64+nt*8+2*ec;
    float* av=acc[m2][nt];
    *(float2*)&Cg[(size_t)row*Cn+col]     = make_float2(av[0],av[1]);
    *(float2*)&Cg[(size_t)(row+8)*Cn+col] = make_float2(av[2],av[3]);
  }
}

// reduce NS split partials + diffusion coefficients (wide grid, 1 elem/thread)
__global__ void k_coef(const float* evals, const float* t, int blk){
  int b=blockIdx.x;
  int idx=blockIdx.y*256+threadIdx.x;
  int k=idx>>7, c=idx&127;
  float s=0.f;
#pragma unroll
  for(int sp=0;sp<NS;sp++) s+=g_Sp[(size_t)(b*NS+sp)*Kn*Cn+idx];
  g_D[(size_t)b*Kn*Cn+idx]=expf(-evals[b*Kn+k]*fmaxf(t[blk*Cn+c],1e-8f))*s;
}

// x = x_in @ Wf + bf
__global__ void k_x0(const float* xi, const float* Wf, const float* bf){
  __shared__ float w[16*128];
  __shared__ float xs[16][17];
  int tid=threadIdx.x;
  for(int i=tid;i<2048;i+=128) w[i]=Wf[i];
  int r0=blockIdx.x*16;
  for(int i=tid;i<256;i+=128) xs[i>>4][i&15]=xi[(size_t)r0*16+i];
  __syncthreads();
  float bv=bf[tid];
#pragma unroll
  for(int rr=0;rr<16;rr++){
    float s=bv;
#pragma unroll
    for(int k=0;k<16;k++) s+=xs[rr][k]*w[k*128+tid];
    g_x[(size_t)(r0+rr)*Cn+tid]=s;
  }
}

extern "C" void kernel_launch(void* const* d_in, const int* in_sizes, int n_in,
                              void* d_out, int out_size){
  const float *x_in=(const float*)d_in[0], *mass=(const float*)d_in[1],
    *evals=(const float*)d_in[2], *evecs=(const float*)d_in[3],
    *gradX=(const float*)d_in[4], *gradY=(const float*)d_in[5],
    *Wf=(const float*)d_in[6], *bf=(const float*)d_in[7],
    *Wl=(const float*)d_in[8], *bl=(const float*)d_in[9],
    *t=(const float*)d_in[10], *Are=(const float*)d_in[11], *Aim=(const float*)d_in[12],
    *W0=(const float*)d_in[13], *b0=(const float*)d_in[14],
    *W1=(const float*)d_in[15], *b1=(const float*)d_in[16],
    *W2=(const float*)d_in[17], *b2=(const float*)d_in[18];
  float* out=(float*)d_out;

  cudaFuncSetAttribute(k_mlp, cudaFuncAttributeMaxDynamicSharedMemorySize, SMEM_MLP);

  float *GXEp,*GYEp,*xp,*xdp,*gxp,*gyp,*Dp;
  cudaGetSymbolAddress((void**)&GXEp,g_GXE); cudaGetSymbolAddress((void**)&GYEp,g_GYE);
  cudaGetSymbolAddress((void**)&xp,g_x);     cudaGetSymbolAddress((void**)&xdp,g_xd);
  cudaGetSymbolAddress((void**)&gxp,g_gx);   cudaGetSymbolAddress((void**)&gyp,g_gy);
  cudaGetSymbolAddress((void**)&Dp,g_D);

  // launch order rearranged: k_pre moved to index 3 so the ncu capture window
  // (which has been landing on launch #3 = k_coef every round) profiles k_pre.
  k_x0<<<Bn*Vn/16,128>>>(x_in,Wf,bf);                     // 0
  k_spec<<<dim3(Bn,NS),256>>>(evecs,mass);                // 1
  k_coef<<<dim3(Bn,64),256>>>(evals,t,0);                 // 2
  // precompute GXE/GYE (block-invariant; only needed before first k_gemm3)
  { GArgs a{}; a.A[0][0]=gradX; a.A[1][0]=gradY; a.C[0]=GXEp; a.C[1]=GYEp;
    a.Bs[0]=evecs; a.sB[0]=(long)Vn*Kn; a.bscz[0][0]=1.f; a.bscz[1][0]=1.f;
    a.kst[0]=Vn/16; a.lda=Vn; a.nseg=1; a.sA=(long)Vn*Vn; a.sC=(long)Vn*Kn; a.act=0;
    a.terms=2;
    k_gemm<<<dim3(32,Bn,2),256>>>(a); }                   // 3  <- profile target

  for(int i=0;i<4;i++){
    if(i>0){
      k_spec<<<dim3(Bn,NS),256>>>(evecs,mass);
      k_coef<<<dim3(Bn,64),256>>>(evals,t,i);
    }
    // x_diff = E@D, gx = GXE@D, gy = GYE@D
    { GArgs a{}; a.A[0][0]=evecs; a.A[1][0]=GXEp; a.A[2][0]=GYEp;
      a.C[0]=xdp; a.C[1]=gxp; a.C[2]=gyp;
      a.Bs[0]=Dp; a.sB[0]=(long)Kn*Cn;
      a.bscz[0][0]=1.f; a.bscz[1][0]=1.f; a.bscz[2][0]=1.f;
      a.kst[0]=Kn/16; a.lda=Kn; a.nseg=1; a.sA=(long)Vn*Kn; a.sC=(long)Vn*Cn; a.act=0;
      a.terms=3;
      k_gemm<<<dim3(32,Bn,3),256>>>(a); }
    // fused: br/bi -> gfeat -> h0 -> h1 -> x += h2
    k_mlp<<<dim3(32,Bn),256,SMEM_MLP>>>(
        Are+(size_t)i*Cn*Cn, Aim+(size_t)i*Cn*Cn,
        W0+(size_t)i*384*Cn, b0+(size_t)i*Cn,
        W1+(size_t)i*Cn*Cn,  b1+(size_t)i*Cn,
        W2+(size_t)i*Cn*Cn,  b2+(size_t)i*Cn);
  }
  // out = x @ Wl + bl
  { GArgs a{}; a.A[0][0]=xp; a.C[0]=out;
    a.Bs[0]=Wl; a.sB[0]=0; a.bscz[0][0]=1.f; a.kst[0]=Kn/16;
    a.lda=Cn; a.nseg=1; a.sA=(long)Vn*Cn; a.sC=(long)Vn*Cn;
    a.bias=bl; a.act=0; a.terms=3;
    k_gemm<<<dim3(32,Bn,1),256>>>(a); }
}

// round 16
// speedup vs baseline: 2.2212x; 1.0123x over previous
#include <cuda_runtime.h>
#include <cuda_fp16.h>
#include <cstdint>

#define Bn 4
#define Vn 4096
#define Kn 128
#define Cn 128
#define NS 32

// ---- scratch (allocation-free rule: __device__ globals) ----
__device__ float g_GXE[Bn*Vn*Kn], g_GYE[Bn*Vn*Kn];
__device__ float g_x[Bn*Vn*Cn];
__device__ float g_Sp[Bn*NS*Kn*Cn], g_D[Bn*Kn*Cn];

#define SA_B 48
#define SB_B 272
#define SETSZ 20992
#define O_AL 6144
#define O_BH 12288
#define O_BL 16640

// k_blk dynamic smem: two staging sets + two resident A-format hi/lo slots
#define S_R1H 41984
#define S_R1L (S_R1H+34816)
#define S_R2H (S_R1L+34816)
#define S_R2L (S_R2H+34816)
#define SMEM_BLK (S_R2L+34816)

__device__ __forceinline__ uint32_t s2u(const void* p){
  uint32_t a; asm("{ .reg .u64 t; cvta.to.shared.u64 t, %1; cvt.u32.u64 %0, t; }":"=r"(a):"l"(p));
  return a;
}
__device__ __forceinline__ uint32_t packh(__half a, __half b){
  __half2 t=__halves2half2(a,b); return *(uint32_t*)&t;
}
__device__ __forceinline__ void split2(float x, __half& h, __half& l){
  h=__float2half_rn(x); l=__float2half_rn(x-__half2float(h));
}
__device__ __forceinline__ void ldsm4(uint32_t a, uint32_t* r){
  asm volatile("ldmatrix.sync.aligned.m8n8.x4.shared.b16 {%0,%1,%2,%3},[%4];"
    :"=r"(r[0]),"=r"(r[1]),"=r"(r[2]),"=r"(r[3]):"r"(a));
}
__device__ __forceinline__ void ldsm4t(uint32_t a, uint32_t* r){
  asm volatile("ldmatrix.sync.aligned.m8n8.x4.trans.shared.b16 {%0,%1,%2,%3},[%4];"
    :"=r"(r[0]),"=r"(r[1]),"=r"(r[2]),"=r"(r[3]):"r"(a));
}
__device__ __forceinline__ void mma16(float* d, const uint32_t* a, uint32_t b0, uint32_t b1){
  asm volatile("mma.sync.aligned.m16n8k16.row.col.f32.f16.f16.f32 "
    "{%0,%1,%2,%3},{%4,%5,%6,%7},{%8,%9},{%0,%1,%2,%3};"
    : "+f"(d[0]),"+f"(d[1]),"+f"(d[2]),"+f"(d[3])
    : "r"(a[0]),"r"(a[1]),"r"(a[2]),"r"(a[3]),"r"(b0),"r"(b1));
}
__device__ __forceinline__ void zacc(float (&a)[2][8][4]){
#pragma unroll
  for(int i=0;i<2;i++)
#pragma unroll
  for(int j=0;j<8;j++)
#pragma unroll
  for(int q=0;q<4;q++) a[i][j][q]=0.f;
}

__device__ __forceinline__ void ldA(const float* A, int lda, int tid, float4* r){
#pragma unroll
  for(int i=0;i<2;i++){ int idx=tid+i*256;
    r[i]=*(const float4*)(A+(size_t)(idx>>2)*lda+((idx&3)<<2)); }
}
__device__ __forceinline__ void ldB(const float* S, int lds, int tid, float4* r){
#pragma unroll
  for(int i=0;i<2;i++){ int idx=tid+i*256;
    r[i]=*(const float4*)(S+(size_t)(idx&15)*lds+(((idx>>4)&31)<<2)); }
}
__device__ __forceinline__ void stA(char* H, char* L, const float4* r, int tid){
#pragma unroll
  for(int i=0;i<2;i++){
    int idx=tid+i*256; int m=idx>>2, kq=(idx&3)<<2;
    float4 v=r[i];
    __half h0,h1,h2,h3,l0,l1,l2,l3;
    split2(v.x,h0,l0); split2(v.y,h1,l1); split2(v.z,h2,l2); split2(v.w,h3,l3);
    *(uint2*)(H+m*SA_B+kq*2)=make_uint2(packh(h0,h1),packh(h2,h3));
    *(uint2*)(L+m*SA_B+kq*2)=make_uint2(packh(l0,l1),packh(l2,l3));
  }
}
__device__ __forceinline__ void stB(char* H, char* L, const float4* r, int tid,
                                    const float* si){
#pragma unroll
  for(int i=0;i<2;i++){
    int idx=tid+i*256; int k=idx&15, nq=((idx>>4)&31)<<2;
    float s=si[i];
    float4 v=r[i];
    __half h0,h1,h2,h3,l0,l1,l2,l3;
    split2(v.x*s,h0,l0); split2(v.y*s,h1,l1); split2(v.z*s,h2,l2); split2(v.w*s,h3,l3);
    *(uint2*)(H+k*SB_B+nq*2)=make_uint2(packh(h0,h1),packh(h2,h3));
    *(uint2*)(L+k*SB_B+nq*2)=make_uint2(packh(l0,l1),packh(l2,l3));
  }
}
// hi-only B staging (2-term kernels: no lo half at all)
__device__ __forceinline__ void stBH(char* H, const float4* r, int tid, const float* si){
#pragma unroll
  for(int i=0;i<2;i++){
    int idx=tid+i*256; int k=idx&15, nq=((idx>>4)&31)<<2;
    float s=si[i];
    float4 v=r[i];
    *(uint2*)(H+k*SB_B+nq*2)=make_uint2(
      packh(__float2half_rn(v.x*s),__float2half_rn(v.y*s)),
      packh(__float2half_rn(v.z*s),__float2half_rn(v.w*s)));
  }
}
// transposed A staging (k_spec): source [16 k][128 m] -> A layout [m][k]
__device__ __forceinline__ void stTA(char* H, char* L, const float4* r, int tid){
#pragma unroll
  for(int i=0;i<2;i++){
    int idx=tid+i*256; int k=idx&15, nq=((idx>>4)&31)<<2;
    float4 v=r[i];
    float e[4]={v.x,v.y,v.z,v.w};
#pragma unroll
    for(int j=0;j<4;j++){
      __half h,l; split2(e[j],h,l);
      *(__half*)(H+(nq+j)*SA_B+k*2)=h;
      *(__half*)(L+(nq+j)*SA_B+k*2)=l;
    }
  }
}

// one 16-deep K step: double-fp16, term-major mma order
__device__ __forceinline__ void gstep(uint32_t aH, uint32_t aL, int sA,
                                      uint32_t bH, uint32_t bL,
                                      float (&acc)[2][8][4], int wm,int wn,int lane,
                                      int three){
  int lr=lane&15, lc=lane>>4;
  uint32_t ah[2][4], al[2][4];
#pragma unroll
  for(int mt=0;mt<2;mt++){
    uint32_t off=(uint32_t)((wm*32+mt*16+lr)*sA+lc*16);
    ldsm4(aH+off, ah[mt]); ldsm4(aL+off, al[mt]);
  }
#pragma unroll
  for(int bt=0;bt<4;bt++){
    uint32_t bh[4], bl[4];
    uint32_t off=(uint32_t)(lr*SB_B+(wn*64+bt*16+lc*8)*2);
    ldsm4t(bH+off, bh);
    if(three) ldsm4t(bL+off, bl);
#pragma unroll
    for(int j=0;j<2;j++)
#pragma unroll
      for(int mt=0;mt<2;mt++)
        mma16(acc[mt][bt*2+j], ah[mt], bh[2*j], bh[2*j+1]);
    if(three){
#pragma unroll
      for(int j=0;j<2;j++)
#pragma unroll
        for(int mt=0;mt<2;mt++)
          mma16(acc[mt][bt*2+j], ah[mt], bl[2*j], bl[2*j+1]);
    }
#pragma unroll
    for(int j=0;j<2;j++)
#pragma unroll
      for(int mt=0;mt<2;mt++)
        mma16(acc[mt][bt*2+j], al[mt], bh[2*j], bh[2*j+1]);
  }
}

struct GArgs {
  const float* A[2];      // [z]
  float* C[2];
  const float* Bs; long sB; int kst;
  int lda;
  long sA, sC;
  const float* bias;
  int terms;
};

// generic tiled GEMM (used for k_pre and final projection)
__global__ void __launch_bounds__(256,2) k_gemm(GArgs ga){
  __shared__ __align__(16) char SBf[2][SETSZ];
  int tid=threadIdx.x, lane=tid&31, w=tid>>5, wm=w&3, wn=w>>2;
  uint32_t sb0=s2u(SBf[0]), sb1=s2u(SBf[1]);
  float acc[2][8][4]={};
  int mt=blockIdx.x, b=blockIdx.y, z=blockIdx.z;
  int three=(ga.terms==3);
  int T=ga.kst;
  const float* As   = ga.A[z] + (size_t)b*ga.sA + (size_t)mt*128*ga.lda;
  const float* Bsrc = ga.Bs   + (size_t)b*ga.sB;
  float4 ra[2], rb[2]; float si[2]={1.f,1.f};
  ldA(As, ga.lda, tid, ra);
  ldB(Bsrc, Cn, tid, rb);
  stA(SBf[0], SBf[0]+O_AL, ra, tid);
  if(three) stB(SBf[0]+O_BH, SBf[0]+O_BL, rb, tid, si);
  else      stBH(SBf[0]+O_BH, rb, tid, si);
  __syncthreads();
  for(int s=0;s<T;s++){
    int more=(s+1<T);
    if(more){
      ldA(As + (s+1)*16, ga.lda, tid, ra);
      ldB(Bsrc + (size_t)(s+1)*16*Cn, Cn, tid, rb);
    }
    uint32_t cb=(s&1)?sb1:sb0;
    gstep(cb, cb+O_AL, SA_B, cb+O_BH, cb+O_BL, acc, wm,wn,lane, three);
    if(more){
      char* nb=SBf[(s+1)&1];
      stA(nb, nb+O_AL, ra, tid);
      if(three) stB(nb+O_BH, nb+O_BL, rb, tid, si);
      else      stBH(nb+O_BH, rb, tid, si);
    }
    __syncthreads();
  }
  float* Cg = ga.C[z] + (size_t)b*ga.sC + (size_t)mt*128*Cn;
  int er=lane>>2, ec=lane&3;
#pragma unroll
  for(int m2=0;m2<2;m2++)
#pragma unroll
  for(int nt=0;nt<8;nt++){
    int row=wm*32+m2*16+er, col=wn*64+nt*8+2*ec;
    float* av=acc[m2][nt];
#pragma unroll
    for(int rr=0;rr<2;rr++){
      int R=row+rr*8;
      float v0=av[rr*2], v1=av[rr*2+1];
      if(ga.bias){ v0+=ga.bias[col]; v1+=ga.bias[col+1]; }
      Cg[(size_t)R*Cn+col]=v0; Cg[(size_t)R*Cn+col+1]=v1;
    }
  }
}

// ---- fused per-block kernel ----
struct MSeg { const float* A; const float* Bw; float sc; int resOff; }; // A==null -> resident

__device__ __forceinline__ void ugemm(char* sm, const MSeg* segs, int nseg,
    float (&acc)[2][8][4], int tid, int wm, int wn, int lane){
  uint32_t sb=s2u(sm);
  int TT=nseg*8;
  float4 ra[2], rb[2]; float si[2];
  {
    const MSeg* c0=&segs[0];
    if(c0->A) ldA(c0->A, Cn, tid, ra);
    ldB(c0->Bw, Cn, tid, rb);
    si[0]=si[1]=c0->sc;
    if(c0->A) stA(sm, sm+O_AL, ra, tid);
    stB(sm+O_BH, sm+O_BL, rb, tid, si);
  }
  __syncthreads();
  for(int g=0; g<TT; g++){
    const MSeg* cur=&segs[g>>3]; int ks=g&7;
    const MSeg* nxt=(g+1<TT)? &segs[(g+1)>>3] : nullptr;
    int nks=(g+1)&7;
    if(nxt){
      if(nxt->A) ldA(nxt->A + nks*16, Cn, tid, ra);
      ldB(nxt->Bw + (size_t)nks*16*Cn, Cn, tid, rb);
      si[0]=si[1]=nxt->sc;
    }
    uint32_t cb=sb+(uint32_t)(g&1)*SETSZ;
    if(cur->A)
      gstep(cb, cb+O_AL, SA_B, cb+O_BH, cb+O_BL, acc, wm, wn, lane, 1);
    else
      gstep(sb+cur->resOff+ks*32, sb+cur->resOff+34816+ks*32, 272,
            cb+O_BH, cb+O_BL, acc, wm, wn, lane, 1);
    if(nxt){
      char* nb=sm+((g+1)&1)*SETSZ;
      if(nxt->A) stA(nb, nb+O_AL, ra, tid);
      stB(nb+O_BH, nb+O_BL, rb, tid, si);
    }
    __syncthreads();
  }
}

// split acc into A-format hi/lo resident slot (optional bias/relu)
__device__ __forceinline__ void epi_split(char* sm, int Hoff,
    float (&acc)[2][8][4], const float* bias, int relu, int wm, int wn, int lane){
  int er=lane>>2, ec=lane&3;
#pragma unroll
  for(int m2=0;m2<2;m2++)
#pragma unroll
  for(int nt=0;nt<8;nt++){
    int row=wm*32+m2*16+er, col=wn*64+nt*8+2*ec;
#pragma unroll
    for(int rr=0;rr<2;rr++){
      int R=row+rr*8;
      float v0=acc[m2][nt][rr*2], v1=acc[m2][nt][rr*2+1];
      if(bias){ v0+=bias[col]; v1+=bias[col+1]; }
      if(relu){ v0=fmaxf(v0,0.f); v1=fmaxf(v1,0.f); }
      __half h0v,l0v,h1v,l1v; split2(v0,h0v,l0v); split2(v1,h1v,l1v);
      *(uint32_t*)(sm+Hoff+R*272+col*2)=packh(h0v,h1v);
      *(uint32_t*)(sm+Hoff+34816+R*272+col*2)=packh(l0v,l1v);
    }
  }
}

__global__ void __launch_bounds__(256) k_blk(
    const float* E, const float* GXE, const float* GYE, const float* D,
    const float* Are,const float* Aim,
    const float* W0,const float* b0,const float* W1,const float* b1,
    const float* W2,const float* b2){
  extern __shared__ char sm[];
  int tid=threadIdx.x, lane=tid&31, w=tid>>5, wm=w&3, wn=w>>2;
  int mt=blockIdx.x, b=blockIdx.y;
  size_t rowoff=(size_t)b*Vn*Cn+(size_t)mt*128*Cn;   // x rows (stride Cn)
  size_t koff  =(size_t)b*Vn*Kn+(size_t)mt*128*Kn;   // E/GXE/GYE rows (stride Kn==Cn)
  const float* Db=D+(size_t)b*Kn*Cn;
  float* xr=g_x+rowoff;
  float acc[2][8][4], brg[2][8][4];
  int er=lane>>2, ec=lane&3;

  // 1. gx = GXE@D -> R1 (hi/lo split, resident)
  zacc(acc);
  { MSeg s[1]={{GXE+koff,Db,1.f,-1}}; ugemm(sm,s,1,acc,tid,wm,wn,lane); }
  epi_split(sm,S_R1H,acc,nullptr,0,wm,wn,lane);
  __syncthreads();
  // 2. gy = GYE@D -> R2
  zacc(acc);
  { MSeg s[1]={{GYE+koff,Db,1.f,-1}}; ugemm(sm,s,1,acc,tid,wm,wn,lane); }
  epi_split(sm,S_R2H,acc,nullptr,0,wm,wn,lane);
  __syncthreads();
  // 3. br = gx@Are - gy@Aim -> registers
  zacc(acc);
  { MSeg s[2]={{nullptr,Are,1.f,S_R1H},{nullptr,Aim,-1.f,S_R2H}};
    ugemm(sm,s,2,acc,tid,wm,wn,lane); }
#pragma unroll
  for(int m2=0;m2<2;m2++)
#pragma unroll
  for(int nt=0;nt<8;nt++)
#pragma unroll
  for(int q=0;q<4;q++) brg[m2][nt][q]=acc[m2][nt][q];
  // 4. bi = gy@Are + gx@Aim; gfeat = tanh(gx*br + gy*bi) -> overwrite R1
  zacc(acc);
  { MSeg s[2]={{nullptr,Are,1.f,S_R2H},{nullptr,Aim,1.f,S_R1H}};
    ugemm(sm,s,2,acc,tid,wm,wn,lane); }
#pragma unroll
  for(int m2=0;m2<2;m2++)
#pragma unroll
  for(int nt=0;nt<8;nt++){
    int row=wm*32+m2*16+er, col=wn*64+nt*8+2*ec;
#pragma unroll
    for(int rr=0;rr<2;rr++){
      int R=row+rr*8;
      __half2 gxh=*(__half2*)(sm+S_R1H+R*272+col*2);
      __half2 gxl=*(__half2*)(sm+S_R1L+R*272+col*2);
      __half2 gyh=*(__half2*)(sm+S_R2H+R*272+col*2);
      __half2 gyl=*(__half2*)(sm+S_R2L+R*272+col*2);
      float gx0=__half2float(gxh.x)+__half2float(gxl.x);
      float gx1=__half2float(gxh.y)+__half2float(gxl.y);
      float gy0=__half2float(gyh.x)+__half2float(gyl.x);
      float gy1=__half2float(gyh.y)+__half2float(gyl.y);
      float v0=tanhf(gx0*brg[m2][nt][rr*2]+gy0*acc[m2][nt][rr*2]);
      float v1=tanhf(gx1*brg[m2][nt][rr*2+1]+gy1*acc[m2][nt][rr*2+1]);
      __half h0v,l0v,h1v,l1v; split2(v0,h0v,l0v); split2(v1,h1v,l1v);
      *(uint32_t*)(sm+S_R1H+R*272+col*2)=packh(h0v,h1v);
      *(uint32_t*)(sm+S_R1L+R*272+col*2)=packh(l0v,l1v);
    }
  }
  __syncthreads();
  // 5. xd = E@D -> overwrite R2 (gy fully consumed above)
  zacc(acc);
  { MSeg s[1]={{E+koff,Db,1.f,-1}}; ugemm(sm,s,1,acc,tid,wm,wn,lane); }
  epi_split(sm,S_R2H,acc,nullptr,0,wm,wn,lane);
  __syncthreads();
  // 6. h0 = relu([x|xd|gf]@W0 + b0) -> overwrite R1 (gf consumed in gemm)
  zacc(acc);
  { MSeg s[3]={{xr,W0,1.f,-1},{nullptr,W0+128*Cn,1.f,S_R2H},{nullptr,W0+256*Cn,1.f,S_R1H}};
    ugemm(sm,s,3,acc,tid,wm,wn,lane); }
  epi_split(sm,S_R1H,acc,b0,1,wm,wn,lane);
  __syncthreads();
  // 7. h1 = relu(h0@W1 + b1) -> overwrite R2
  zacc(acc);
  { MSeg s[1]={{nullptr,W1,1.f,S_R1H}}; ugemm(sm,s,1,acc,tid,wm,wn,lane); }
  epi_split(sm,S_R2H,acc,b1,1,wm,wn,lane);
  __syncthreads();
  // 8. x += h1@W2 + b2
  zacc(acc);
  { MSeg s[1]={{nullptr,W2,1.f,S_R2H}}; ugemm(sm,s,1,acc,tid,wm,wn,lane); }
#pragma unroll
  for(int m2=0;m2<2;m2++)
#pragma unroll
  for(int nt=0;nt<8;nt++){
    int row=wm*32+m2*16+er, col=wn*64+nt*8+2*ec;
#pragma unroll
    for(int rr=0;rr<2;rr++){
      int R=row+rr*8;
      float v0=acc[m2][nt][rr*2]+b2[col]+xr[(size_t)R*Cn+col];
      float v1=acc[m2][nt][rr*2+1]+b2[col+1]+xr[(size_t)R*Cn+col+1];
      xr[(size_t)R*Cn+col]=v0; xr[(size_t)R*Cn+col+1]=v1;
    }
  }
}

// x_spec split-K partials
__global__ void __launch_bounds__(256,2) k_spec(const float* E, const float* mass){
  __shared__ __align__(16) char SBf[2][SETSZ];
  int tid=threadIdx.x, lane=tid&31, w=tid>>5, wm=w&3, wn=w>>2;
  uint32_t sb0=s2u(SBf[0]), sb1=s2u(SBf[1]);
  float acc[2][8][4]={};
  int b=blockIdx.x, sp=blockIdx.y;
  const float* Eb=E+(size_t)b*Vn*Kn;
  const float* Xb=g_x+(size_t)b*Vn*Cn;
  const float* Mb=mass+(size_t)b*Vn;
  int v0=sp*(Vn/NS);
  const int T=(Vn/NS)/16;
  float4 ra[2], rb[2]; float ms[2];
  ldB(Eb+(size_t)v0*Kn, Kn, tid, ra);
  ldB(Xb+(size_t)v0*Cn, Cn, tid, rb);
#pragma unroll
  for(int i=0;i<2;i++){ int idx=tid+i*256; ms[i]=Mb[v0+(idx&15)]; }
  stTA(SBf[0], SBf[0]+O_AL, ra, tid);
  stB(SBf[0]+O_BH, SBf[0]+O_BL, rb, tid, ms);
  __syncthreads();
  for(int s=0;s<T;s++){
    int more=(s+1<T);
    if(more){
      int v=v0+(s+1)*16;
      ldB(Eb+(size_t)v*Kn, Kn, tid, ra);
      ldB(Xb+(size_t)v*Cn, Cn, tid, rb);
#pragma unroll
      for(int i=0;i<2;i++){ int idx=tid+i*256; ms[i]=Mb[v+(idx&15)]; }
    }
    uint32_t cb=(s&1)?sb1:sb0;
    gstep(cb, cb+O_AL, SA_B, cb+O_BH, cb+O_BL, acc, wm,wn,lane, 1);
    if(more){
      char* nb=SBf[(s+1)&1];
      stTA(nb, nb+O_AL, ra, tid);
      stB(nb+O_BH, nb+O_BL, rb, tid, ms);
    }
    __syncthreads();
  }
  float* Cg=g_Sp+(size_t)(b*NS+sp)*Kn*Cn;
  int er=lane>>2, ec=lane&3;
#pragma unroll
  for(int m2=0;m2<2;m2++)
#pragma unroll
  for(int nt=0;nt<8;nt++){
    int row=wm*32+m2*16+er, col=wn*64+nt*8+2*ec;
    float* av=acc[m2][nt];
    *(float2*)&Cg[(size_t)row*Cn+col]     = make_float2(av[0],av[1]);
    *(float2*)&Cg[(size_t)(row+8)*Cn+col] = make_float2(av[2],av[3]);
  }
}

__global__ void k_coef(const float* evals, const float* t, int blk){
  int b=blockIdx.x;
  int idx=blockIdx.y*256+threadIdx.x;
  int k=idx>>7, c=idx&127;
  float s=0.f;
#pragma unroll
  for(int sp=0;sp<NS;sp++) s+=g_Sp[(size_t)(b*NS+sp)*Kn*Cn+idx];
  g_D[(size_t)b*Kn*Cn+idx]=expf(-evals[b*Kn+k]*fmaxf(t[blk*Cn+c],1e-8f))*s;
}

__global__ void k_x0(const float* xi, const float* Wf, const float* bf){
  __shared__ float w[16*128];
  __shared__ float xs[16][17];
  int tid=threadIdx.x;
  for(int i=tid;i<2048;i+=128) w[i]=Wf[i];
  int r0=blockIdx.x*16;
  for(int i=tid;i<256;i+=128) xs[i>>4][i&15]=xi[(size_t)r0*16+i];
  __syncthreads();
  float bv=bf[tid];
#pragma unroll
  for(int rr=0;rr<16;rr++){
    float s=bv;
#pragma unroll
    for(int k=0;k<16;k++) s+=xs[rr][k]*w[k*128+tid];
    g_x[(size_t)(r0+rr)*Cn+tid]=s;
  }
}

extern "C" void kernel_launch(void* const* d_in, const int* in_sizes, int n_in,
                              void* d_out, int out_size){
  const float *x_in=(const float*)d_in[0], *mass=(const float*)d_in[1],
    *evals=(const float*)d_in[2], *evecs=(const float*)d_in[3],
    *gradX=(const float*)d_in[4], *gradY=(const float*)d_in[5],
    *Wf=(const float*)d_in[6], *bf=(const float*)d_in[7],
    *Wl=(const float*)d_in[8], *bl=(const float*)d_in[9],
    *t=(const float*)d_in[10], *Are=(const float*)d_in[11], *Aim=(const float*)d_in[12],
    *W0=(const float*)d_in[13], *b0=(const float*)d_in[14],
    *W1=(const float*)d_in[15], *b1=(const float*)d_in[16],
    *W2=(const float*)d_in[17], *b2=(const float*)d_in[18];
  float* out=(float*)d_out;

  cudaFuncSetAttribute(k_blk, cudaFuncAttributeMaxDynamicSharedMemorySize, SMEM_BLK);

  float *GXEp,*GYEp,*xp,*Dp;
  cudaGetSymbolAddress((void**)&GXEp,g_GXE); cudaGetSymbolAddress((void**)&GYEp,g_GYE);
  cudaGetSymbolAddress((void**)&xp,g_x);     cudaGetSymbolAddress((void**)&Dp,g_D);

  k_x0<<<Bn*Vn/16,128>>>(x_in,Wf,bf);                     // 0
  k_spec<<<dim3(Bn,NS),256>>>(evecs,mass);                // 1
  k_coef<<<dim3(Bn,64),256>>>(evals,t,0);                 // 2
  // k_pre at launch index 3 (profile window target): GXE/GYE, 2-term split
  { GArgs a{}; a.A[0]=gradX; a.A[1]=gradY; a.C[0]=GXEp; a.C[1]=GYEp;
    a.Bs=evecs; a.sB=(long)Vn*Kn; a.kst=Vn/16; a.lda=Vn;
    a.sA=(long)Vn*Vn; a.sC=(long)Vn*Kn; a.terms=2;
    k_gemm<<<dim3(32,Bn,2),256>>>(a); }                   // 3

  for(int i=0;i<4;i++){
    if(i>0){
      k_spec<<<dim3(Bn,NS),256>>>(evecs,mass);
      k_coef<<<dim3(Bn,64),256>>>(evals,t,i);
    }
    k_blk<<<dim3(32,Bn),256,SMEM_BLK>>>(
        evecs, GXEp, GYEp, Dp,
        Are+(size_t)i*Cn*Cn, Aim+(size_t)i*Cn*Cn,
        W0+(size_t)i*384*Cn, b0+(size_t)i*Cn,
        W1+(size_t)i*Cn*Cn,  b1+(size_t)i*Cn,
        W2+(size_t)i*Cn*Cn,  b2+(size_t)i*Cn);
  }
  // out = x @ Wl + bl
  { GArgs a{}; a.A[0]=xp; a.C[0]=out;
    a.Bs=Wl; a.sB=0; a.kst=Kn/16; a.lda=Cn;
    a.sA=(long)Vn*Cn; a.sC=(long)Vn*Cn; a.bias=bl; a.terms=3;
    k_gemm<<<dim3(32,Bn,1),256>>>(a); }
}